// round 8
// baseline (speedup 1.0000x reference)
#include <cuda_runtime.h>
#include <cuda_bf16.h>
#include <math.h>
#include <stdint.h>

// ---------------- problem constants ----------------
#define T_    4
#define B_    32
#define N_    196
#define C_    384
#define H_    8
#define D_    48
#define HID_  1536
#define TB_   128           // T*B
#define NC_   75264         // N*C
#define BNC_  2408448       // B*N*C
#define TBN_  25088         // T*B*N
#define BN_   6272          // B*N
#define MH_   9633792       // BN_*HID_ == TBN_*C_

// ---------------- scratch (device globals) ----------------
__device__ float g_bq[MH_];
__device__ float g_bk[MH_];
__device__ float g_bv[MH_];
__device__ float g_ab[MH_];
__device__ float g_af[MH_];
__device__ float g_curr[4 * MH_];
__device__ float g_syn[MH_];
__device__ float g_mem[MH_];
__device__ float g_R[MH_];
__device__ float g_l[MH_];
__device__ float g_ga[MH_];
__device__ float g_gl[MH_];
__device__ float g_fu[MH_];
__device__ float g_o[MH_];
__device__ float g_part[98 * 768];
__device__ float g_stats[768];
// int8 spike buffers (exactly 0/1), 16B-aligned for vector/cp.async access
__device__ __align__(16) int8_t g_sq[MH_];
__device__ __align__(16) int8_t g_sk[MH_];
__device__ __align__(16) int8_t g_sv[MH_];
__device__ __align__(16) int8_t g_abb[MH_];
__device__ __align__(16) int8_t g_afb[MH_];
__device__ __align__(16) int8_t g_spkb[4 * MH_];
__device__ __align__(16) int8_t g_lfb[MH_];
// 4-digit int8 weight decompositions (binary-input GEMMs only)
#define CC_ (C_ * C_)
#define HC_ (HID_ * C_)
#define HH_ (HID_ * HID_)
__device__ __align__(16) int8_t g_apd[4 * CC_];
__device__ __align__(16) int8_t g_watd[4 * CC_];
__device__ __align__(16) int8_t g_wlsd[4 * CC_];
__device__ __align__(16) int8_t g_fc2d[4 * HC_];
__device__ __align__(16) int8_t g_recd[4 * HH_];

// ---------------- helpers ----------------
__device__ __forceinline__ uint32_t smem_to_u32(const void* p) {
    uint32_t a;
    asm("{ .reg .u64 t; cvta.to.shared.u64 t, %1; cvt.u32.u64 %0, t; }" : "=r"(a) : "l"(p));
    return a;
}

#define LDSM4(R0, R1, R2, R3, ADDR) \
    asm volatile("ldmatrix.sync.aligned.m8n8.x4.shared.b16 {%0,%1,%2,%3}, [%4];" \
                 : "=r"(R0), "=r"(R1), "=r"(R2), "=r"(R3) : "r"(ADDR))

#define IMMA16832(D, A0, A1, A2, A3, B0, B1) \
    asm volatile("mma.sync.aligned.m16n8k32.row.col.s32.s8.s8.s32 " \
                 "{%0,%1,%2,%3}, {%4,%5,%6,%7}, {%8,%9}, {%0,%1,%2,%3};" \
                 : "+r"((D)[0]), "+r"((D)[1]), "+r"((D)[2]), "+r"((D)[3]) \
                 : "r"(A0), "r"(A1), "r"(A2), "r"(A3), "r"(B0), "r"(B1))

#define CP_ASYNC16(DST, SRC) \
    asm volatile("cp.async.cg.shared.global [%0], [%1], 16;" :: "r"(DST), "l"(SRC))
#define CP_COMMIT() asm volatile("cp.async.commit_group;" ::: "memory")
#define CP_WAIT0()  asm volatile("cp.async.wait_group 0;" ::: "memory")

// ====== IMMA exact 4-digit GEMM v2: C[M,Nn] = A(0/1) @ W[Nn,K]^T + bias ======
// W decomposed as w = 2 * sum_j d_j * 128^-(j+1), digits int8 (exact).
// int32 accumulation (exact); fp32 fold once per digit.
// 128x128 tile, 512 threads / 16 warps (4m x 4n), warp tile 32x32.
// K-chunks of 64, double-buffered smem, cp.async pipeline.
// smem: A[2] @ 0/10240, W[2] @ 20480/30720, rows stride 80B (conflict-free ldmatrix).
__global__ __launch_bounds__(512, 1)
void igemm4_nt(const int8_t* __restrict__ A, const int8_t* __restrict__ Wd,
               const float* __restrict__ bias, float* __restrict__ C,
               int M, int Nn, int K) {
    __shared__ __align__(16) char sm[40960];
    const int tid = threadIdx.x;
    const int lane = tid & 31;
    const int wid = tid >> 5;
    const int warp_m = wid & 3;       // 0..3
    const int warp_n = wid >> 2;      // 0..3
    const int bm = blockIdx.y * 128;
    const int bn = blockIdx.x * 128;
    const uint32_t smb = smem_to_u32(sm);

    float accf[2][4][4];
    int   acci[2][4][4];
#pragma unroll
    for (int i = 0; i < 2; i++)
#pragma unroll
        for (int j = 0; j < 4; j++)
#pragma unroll
            for (int r = 0; r < 4; r++) { accf[i][j][r] = 0.0f; acci[i][j][r] = 0; }

    const int nch = K >> 6;           // 64-wide K chunks per digit (6 or 24)
    const int totch = 4 * nch;
    const size_t wstride = (size_t)Nn * K;

    // cp.async mapping: 512 threads x 16B = 8KB = one 128x64 tile
    const int grow = tid >> 2;        // 0..127
    const int gseg = tid & 3;         // 16B segment within 64B row-chunk
    const uint32_t sdst = (uint32_t)(grow * 80 + gseg * 16);
    const int64_t gsrcA = (int64_t)(bm + grow) * K + gseg * 16;
    const int64_t gsrcW = (int64_t)(bn + grow) * K + gseg * 16;

    // ldmatrix per-lane address components (warp tile 32x32)
    const int arow0 = warp_m * 32 + (lane & 15);
    const int akc0 = lane >> 4;                            // 16B half within k32
    const int brow0 = warp_n * 32 + ((lane & 7) | ((lane & 16) >> 1));
    const int bkc0 = (lane >> 3) & 1;

    const float wj_tab[4] = {0.015625f, 1.220703125e-4f,
                             9.5367431640625e-7f, 7.450580596923828e-9f};

    // prologue: chunk 0 (digit 0, kc 0) -> buffer 0
    CP_ASYNC16(smb + sdst, A + gsrcA);
    CP_ASYNC16(smb + 20480u + sdst, Wd + gsrcW);
    CP_COMMIT();
    CP_WAIT0();
    __syncthreads();

    int kc_next = 1, dig_next = 0;
    if (kc_next == nch) { kc_next = 0; dig_next = 1; }

    for (int ch = 0; ch < totch; ch++) {
        const int cur = ch & 1;
        const bool more = (ch + 1 < totch);
        if (more) {
            const uint32_t nb = (uint32_t)(cur ^ 1) * 10240u;
            CP_ASYNC16(smb + nb + sdst, A + gsrcA + (int64_t)kc_next * 64);
            CP_ASYNC16(smb + 20480u + nb + sdst,
                       Wd + (size_t)dig_next * wstride + gsrcW + (int64_t)kc_next * 64);
            CP_COMMIT();
        }
        // compute on buffer cur: two k32 steps
        const uint32_t baseA = smb + (uint32_t)cur * 10240u;
        const uint32_t baseB = smb + 20480u + (uint32_t)cur * 10240u;
#pragma unroll
        for (int ks = 0; ks < 2; ks++) {
            uint32_t a[2][4];
#pragma unroll
            for (int mt = 0; mt < 2; mt++) {
                const uint32_t ad = baseA + (uint32_t)(arow0 + mt * 16) * 80u
                                    + (uint32_t)(ks * 32 + akc0 * 16);
                LDSM4(a[mt][0], a[mt][1], a[mt][2], a[mt][3], ad);
            }
            uint32_t b[2][4];
#pragma unroll
            for (int np = 0; np < 2; np++) {
                const uint32_t bd = baseB + (uint32_t)(brow0 + np * 16) * 80u
                                    + (uint32_t)(ks * 32 + bkc0 * 16);
                LDSM4(b[np][0], b[np][1], b[np][2], b[np][3], bd);
            }
#pragma unroll
            for (int mt = 0; mt < 2; mt++) {
#pragma unroll
                for (int nt = 0; nt < 4; nt++) {
                    const int np = nt >> 1;
                    const int hb = (nt & 1) * 2;
                    IMMA16832(acci[mt][nt], a[mt][0], a[mt][1], a[mt][2], a[mt][3],
                              b[np][hb], b[np][hb + 1]);
                }
            }
        }
        // digit boundary: fold int32 -> fp32
        if (((ch + 1) % nch) == 0) {
            const float wj = wj_tab[ch / nch];
#pragma unroll
            for (int mt = 0; mt < 2; mt++)
#pragma unroll
                for (int nt = 0; nt < 4; nt++)
#pragma unroll
                    for (int r = 0; r < 4; r++) {
                        accf[mt][nt][r] = fmaf((float)acci[mt][nt][r], wj, accf[mt][nt][r]);
                        acci[mt][nt][r] = 0;
                    }
        }
        if (more) {
            CP_WAIT0();
            __syncthreads();
            if (++kc_next == nch) { kc_next = 0; dig_next++; }
        }
    }

    // epilogue with bias
#pragma unroll
    for (int mt = 0; mt < 2; mt++) {
        const int m0 = bm + warp_m * 32 + mt * 16 + (lane >> 2);
#pragma unroll
        for (int nt = 0; nt < 4; nt++) {
            const int n0 = bn + warp_n * 32 + nt * 8 + 2 * (lane & 3);
            const float2 bv = *(const float2*)&bias[n0];
            float2 v0, v1;
            v0.x = accf[mt][nt][0] + bv.x; v0.y = accf[mt][nt][1] + bv.y;
            v1.x = accf[mt][nt][2] + bv.x; v1.y = accf[mt][nt][3] + bv.y;
            *(float2*)&C[(size_t)m0 * Nn + n0] = v0;
            *(float2*)&C[(size_t)(m0 + 8) * Nn + n0] = v1;
        }
    }
}

// ================= fp32 SGEMM (round-2 proven, bitwise unchanged) =================
#define BM 128
#define BN 128
#define BK 8

__global__ __launch_bounds__(256, 2)
void sgemm_nt(const float* __restrict__ A, const float* __restrict__ W,
              const float* __restrict__ bias, float* __restrict__ C,
              int M, int N, int K) {
    __shared__ float As[2][BK][BM];
    __shared__ float Bs[2][BK][BN];

    const int tid = threadIdx.x;
    const int bm = blockIdx.y * BM;
    const int bn = blockIdx.x * BN;

    const int lr = tid >> 1;
    const int lc = (tid & 1) * 4;
    const float* Ap = A + (size_t)(bm + lr) * K + lc;
    const float* Wp = W + (size_t)(bn + lr) * K + lc;

    const int tx = tid & 15;
    const int ty = tid >> 4;

    float acc[8][8] = {};

    float4 av = *(const float4*)Ap;
    float4 wv = *(const float4*)Wp;
    As[0][lc + 0][lr] = av.x; As[0][lc + 1][lr] = av.y;
    As[0][lc + 2][lr] = av.z; As[0][lc + 3][lr] = av.w;
    Bs[0][lc + 0][lr] = wv.x; Bs[0][lc + 1][lr] = wv.y;
    Bs[0][lc + 2][lr] = wv.z; Bs[0][lc + 3][lr] = wv.w;
    __syncthreads();

    const int nk = K / BK;
    for (int kt = 0; kt < nk; kt++) {
        const int cur = kt & 1;
        if (kt + 1 < nk) {
            av = *(const float4*)(Ap + (size_t)(kt + 1) * BK);
            wv = *(const float4*)(Wp + (size_t)(kt + 1) * BK);
        }
#pragma unroll
        for (int kk = 0; kk < BK; kk++) {
            float4 a0 = *(const float4*)&As[cur][kk][ty * 4];
            float4 a1 = *(const float4*)&As[cur][kk][ty * 4 + 64];
            float4 b0 = *(const float4*)&Bs[cur][kk][tx * 4];
            float4 b1 = *(const float4*)&Bs[cur][kk][tx * 4 + 64];
            float a[8] = {a0.x, a0.y, a0.z, a0.w, a1.x, a1.y, a1.z, a1.w};
            float b[8] = {b0.x, b0.y, b0.z, b0.w, b1.x, b1.y, b1.z, b1.w};
#pragma unroll
            for (int i = 0; i < 8; i++)
#pragma unroll
                for (int j = 0; j < 8; j++)
                    acc[i][j] += a[i] * b[j];
        }
        if (kt + 1 < nk) {
            const int nxt = cur ^ 1;
            As[nxt][lc + 0][lr] = av.x; As[nxt][lc + 1][lr] = av.y;
            As[nxt][lc + 2][lr] = av.z; As[nxt][lc + 3][lr] = av.w;
            Bs[nxt][lc + 0][lr] = wv.x; Bs[nxt][lc + 1][lr] = wv.y;
            Bs[nxt][lc + 2][lr] = wv.z; Bs[nxt][lc + 3][lr] = wv.w;
            __syncthreads();
        }
    }

#pragma unroll
    for (int i = 0; i < 8; i++) {
        const int row = bm + ty * 4 + (i & 3) + ((i >> 2) << 6);
#pragma unroll
        for (int jb = 0; jb < 2; jb++) {
            const int col = bn + tx * 4 + jb * 64;
            float4 bv4 = *(const float4*)&bias[col];
            float4 v;
            v.x = acc[i][jb * 4 + 0] + bv4.x;
            v.y = acc[i][jb * 4 + 1] + bv4.y;
            v.z = acc[i][jb * 4 + 2] + bv4.z;
            v.w = acc[i][jb * 4 + 3] + bv4.w;
            *(float4*)&C[(size_t)row * N + col] = v;
        }
    }
}

// ---------------- exact 4-digit int8 decomposition: w = 2 * sum d_j 128^-(j+1) ----------------
__global__ void split_digits(const float* __restrict__ w, int8_t* __restrict__ d, long n) {
    long i = (long)blockIdx.x * blockDim.x + threadIdx.x;
    if (i >= n) return;
    float r = w[i] * 0.5f;            // exact (|w| < 2)
#pragma unroll
    for (int j = 0; j < 4; j++) {
        float rj = r * 128.0f;        // exact
        float dj = rintf(rj);
        r = rj - dj;                  // exact
        d[(size_t)j * n + i] = (int8_t)(int)dj;
    }
}

// ---------------- LIF scan: float in -> int8 spikes out ----------------
__global__ void lif_seq_i8(const float* __restrict__ in, int8_t* __restrict__ out,
                           int steps, long stride, long nelem,
                           const float* __restrict__ lif_w, int widx) {
    long idx = (long)blockIdx.x * blockDim.x + threadIdx.x;
    if (idx >= nelem) return;
    const float decay = 1.0f / (1.0f + expf(-lif_w[widx]));
    float v = 0.0f;
    float xs[4];
#pragma unroll
    for (int t = 0; t < 4; t++)
        if (t < steps) xs[t] = in[(long)t * stride + idx];
    for (int t = 0; t < steps; t++) {
        float x = xs[t & 3];
        if (t + 4 < steps) xs[t & 3] = in[(long)(t + 4) * stride + idx];
        v = v + (x - v) * decay;
        int8_t s = (v >= 1.0f) ? 1 : 0;
        out[(long)t * stride + idx] = s;
        if (s) v = 0.0f;
    }
}

// ---------------- spiking attention (int8 spikes), one block per (tb, h) ----------------
__global__ __launch_bounds__(256)
void attn_kernel(const int8_t* __restrict__ sq, const int8_t* __restrict__ sk,
                 const int8_t* __restrict__ sv, float* __restrict__ abuf) {
    const int tb = blockIdx.x >> 3;
    const int h = blockIdx.x & 7;
    __shared__ unsigned long long qb[N_], kb[N_], vb[N_];
    __shared__ unsigned char cnt[N_ * 200];
    const int tid = threadIdx.x;

    for (int i = tid; i < N_; i += 256) { qb[i] = 0ull; kb[i] = 0ull; vb[i] = 0ull; }
    __syncthreads();

    const long base = (long)tb * NC_ + h * D_;
    for (int e = tid; e < N_ * D_; e += 256) {
        int n = e / D_, d = e % D_;
        long off = base + (long)n * C_ + d;
        unsigned long long bit = 1ull << d;
        if (sq[off]) atomicOr(&qb[n], bit);
        if (sk[off]) atomicOr(&kb[n], bit);
        if (sv[off]) atomicOr(&vb[n], bit);
    }
    __syncthreads();

    for (int i = tid; i < N_ * N_; i += 256) {
        int n = i / N_, m = i - n * N_;
        cnt[n * 200 + m] = (unsigned char)__popcll(qb[n] & kb[m]);
    }
    __syncthreads();

    const float scale = 0.14433756729740643f;  // 48^-0.5
    for (int o = tid; o < N_ * D_; o += 256) {
        int n = o / D_, d = o - n * D_;
        const unsigned char* crow = &cnt[n * 200];
        int acc = 0;
#pragma unroll 4
        for (int m = 0; m < N_; m++)
            acc += (int)crow[m] * (int)((vb[m] >> d) & 1ull);
        abuf[(long)tb * NC_ + h * (D_ * N_) + d * N_ + n] = scale * (float)acc;
    }
}

// ---------------- LSM elementwise steps (int8 spikes) ----------------
__global__ void lsm_step0(const float* __restrict__ curr, const float* __restrict__ rec_b,
                          float* __restrict__ syn, float* __restrict__ mem,
                          int8_t* __restrict__ spk) {
    long idx = (long)blockIdx.x * blockDim.x + threadIdx.x;
    if (idx >= (long)MH_) return;
    int hc = (int)(idx % HID_);
    float s = curr[idx] + rec_b[hc];
    syn[idx] = s;
    mem[idx] = s;
    spk[idx] = (s - 1.0f >= 0.0f) ? 1 : 0;
}

__global__ void lsm_step(const float* __restrict__ curr_t, const float* __restrict__ R,
                         float* __restrict__ syn, float* __restrict__ mem,
                         const int8_t* __restrict__ spk_prev, int8_t* __restrict__ spk_out) {
    long idx = (long)blockIdx.x * blockDim.x + threadIdx.x;
    if (idx >= (long)MH_) return;
    float sp = spk_prev[idx] ? 1.0f : 0.0f;
    float s = 0.9f * syn[idx] + curr_t[idx] + R[idx];
    float m = 0.8f * mem[idx] + s - sp;
    syn[idx] = s;
    mem[idx] = m;
    spk_out[idx] = (m - 1.0f >= 0.0f) ? 1 : 0;
}

// ---------------- BatchNorm stats (deterministic 2-stage) ----------------
__global__ void bn_partial(const float* __restrict__ X, float* __restrict__ part) {
    int c = threadIdx.x;
    long r0 = (long)blockIdx.x * 256;
    float s = 0.0f, s2 = 0.0f;
    for (int r = 0; r < 256; r++) {
        float v = X[(r0 + r) * C_ + c];
        s += v;
        s2 += v * v;
    }
    part[blockIdx.x * 768 + c] = s;
    part[blockIdx.x * 768 + 384 + c] = s2;
}

__global__ void bn_finalize(const float* __restrict__ part, float* __restrict__ stats) {
    int c = threadIdx.x;
    float s = 0.0f, s2 = 0.0f;
    for (int p = 0; p < 98; p++) {
        s += part[p * 768 + c];
        s2 += part[p * 768 + 384 + c];
    }
    const float inv = 1.0f / 25088.0f;
    float m = s * inv;
    float var = s2 * inv - m * m;
    stats[c] = m;
    stats[384 + c] = 1.0f / sqrtf(var + 1e-5f);
}

// ---------------- BN-apply + 4-step LIF -> int8 spikes ----------------
__global__ void bn_lif4_i8(const float* __restrict__ lin, int8_t* __restrict__ out,
                           const float* __restrict__ stats,
                           const float* __restrict__ gamma, const float* __restrict__ beta,
                           const float* __restrict__ lif_w, int widx) {
    long idx = (long)blockIdx.x * blockDim.x + threadIdx.x;
    if (idx >= (long)BNC_) return;
    int c = (int)(idx % C_);
    float mu = stats[c], rstd = stats[384 + c];
    float gg = gamma[c], bb = beta[c];
    float decay = 1.0f / (1.0f + expf(-lif_w[widx]));
    float v = 0.0f;
    float xs[4];
#pragma unroll
    for (int t = 0; t < 4; t++) xs[t] = lin[(long)t * BNC_ + idx];
#pragma unroll
    for (int t = 0; t < 4; t++) {
        float xv = (xs[t] - mu) * rstd * gg + bb;
        v = v + (xv - v) * decay;
        int8_t s = (v >= 1.0f) ? 1 : 0;
        if (s) v = 0.0f;
        out[(long)t * BNC_ + idx] = s;
    }
}

// ---------------- BN-apply + 4-step LIF + residual -> float out ----------------
__global__ void bn_lif4_res(const float* __restrict__ lin, float* __restrict__ out,
                            const float* __restrict__ stats,
                            const float* __restrict__ gamma, const float* __restrict__ beta,
                            const float* __restrict__ lif_w, int widx,
                            const float* __restrict__ xadd) {
    long idx = (long)blockIdx.x * blockDim.x + threadIdx.x;
    if (idx >= (long)BNC_) return;
    int c = (int)(idx % C_);
    float mu = stats[c], rstd = stats[384 + c];
    float gg = gamma[c], bb = beta[c];
    float decay = 1.0f / (1.0f + expf(-lif_w[widx]));
    float v = 0.0f;
    float xs[4];
#pragma unroll
    for (int t = 0; t < 4; t++) xs[t] = lin[(long)t * BNC_ + idx];
#pragma unroll
    for (int t = 0; t < 4; t++) {
        long o = (long)t * BNC_ + idx;
        float xv = (xs[t] - mu) * rstd * gg + bb;
        v = v + (xv - v) * decay;
        float s = (v >= 1.0f) ? 1.0f : 0.0f;
        v *= (1.0f - s);
        out[o] = xadd[o] + s;
    }
}

// ---------------- ARIG fusion: int8 spikes + float gates -> float fu ----------------
__global__ void fuse_kernel(const int8_t* __restrict__ afb, const int8_t* __restrict__ lfb,
                            const float* __restrict__ ga, const float* __restrict__ gl,
                            float* __restrict__ fu) {
    long idx = (long)blockIdx.x * blockDim.x + threadIdx.x;
    if (idx >= (long)MH_) return;
    float a = afb[idx] ? 1.0f : 0.0f;
    float l = lfb[idx] ? 1.0f : 0.0f;
    float gate_attn = 1.0f / (1.0f + expf(-gl[idx]));
    float gate_lsm  = 1.0f / (1.0f + expf(-ga[idx]));
    fu[idx] = a * gate_attn + l * gate_lsm;
}

// ---------------- launch ----------------
extern "C" void kernel_launch(void* const* d_in, const int* in_sizes, int n_in,
                              void* d_out, int out_size) {
    const float* x      = (const float*)d_in[0];
    const float* q_w    = (const float*)d_in[1];
    const float* q_b    = (const float*)d_in[2];
    const float* k_w    = (const float*)d_in[3];
    const float* k_b    = (const float*)d_in[4];
    const float* v_w    = (const float*)d_in[5];
    const float* v_b    = (const float*)d_in[6];
    const float* ap_w   = (const float*)d_in[7];
    const float* ap_b   = (const float*)d_in[8];
    const float* fc1_w  = (const float*)d_in[9];
    const float* fc1_b  = (const float*)d_in[10];
    const float* rec_w  = (const float*)d_in[11];
    const float* rec_b  = (const float*)d_in[12];
    const float* fc2_w  = (const float*)d_in[13];
    const float* fc2_b  = (const float*)d_in[14];
    const float* bnl_g  = (const float*)d_in[15];
    const float* bnl_b  = (const float*)d_in[16];
    const float* watt_w = (const float*)d_in[17];
    const float* watt_b = (const float*)d_in[18];
    const float* wlsm_w = (const float*)d_in[19];
    const float* wlsm_b = (const float*)d_in[20];
    const float* fp_w   = (const float*)d_in[21];
    const float* fp_b   = (const float*)d_in[22];
    const float* bnf_g  = (const float*)d_in[23];
    const float* bnf_b  = (const float*)d_in[24];
    const float* lif_w  = (const float*)d_in[25];
    float* out = (float*)d_out;

    float *bq, *bk, *bv, *ab, *af, *curr, *syn, *mem, *R, *l, *ga, *gl, *fu, *o, *part, *stats;
    cudaGetSymbolAddress((void**)&bq, g_bq);     cudaGetSymbolAddress((void**)&bk, g_bk);
    cudaGetSymbolAddress((void**)&bv, g_bv);     cudaGetSymbolAddress((void**)&ab, g_ab);
    cudaGetSymbolAddress((void**)&af, g_af);     cudaGetSymbolAddress((void**)&curr, g_curr);
    cudaGetSymbolAddress((void**)&syn, g_syn);   cudaGetSymbolAddress((void**)&mem, g_mem);
    cudaGetSymbolAddress((void**)&R, g_R);       cudaGetSymbolAddress((void**)&l, g_l);
    cudaGetSymbolAddress((void**)&ga, g_ga);     cudaGetSymbolAddress((void**)&gl, g_gl);
    cudaGetSymbolAddress((void**)&fu, g_fu);     cudaGetSymbolAddress((void**)&o, g_o);
    cudaGetSymbolAddress((void**)&part, g_part); cudaGetSymbolAddress((void**)&stats, g_stats);
    int8_t *sq, *sk, *sv, *abb, *afb, *spkb, *lfb;
    cudaGetSymbolAddress((void**)&sq, g_sq);     cudaGetSymbolAddress((void**)&sk, g_sk);
    cudaGetSymbolAddress((void**)&sv, g_sv);     cudaGetSymbolAddress((void**)&abb, g_abb);
    cudaGetSymbolAddress((void**)&afb, g_afb);   cudaGetSymbolAddress((void**)&spkb, g_spkb);
    cudaGetSymbolAddress((void**)&lfb, g_lfb);
    int8_t *apd, *watd, *wlsd, *fc2d, *recd;
    cudaGetSymbolAddress((void**)&apd, g_apd);
    cudaGetSymbolAddress((void**)&watd, g_watd);
    cudaGetSymbolAddress((void**)&wlsd, g_wlsd);
    cudaGetSymbolAddress((void**)&fc2d, g_fc2d);
    cudaGetSymbolAddress((void**)&recd, g_recd);

    const int nb75k = (NC_ + 255) / 256;
    const int nbBNC = (BNC_ + 255) / 256;
    const int nbMH  = (MH_ + 255) / 256;
    const dim3 gC(C_ / 128, TBN_ / 128);   // (3, 196)
    const dim3 gH(HID_ / 128, TBN_ / 128); // (12, 196)
    const dim3 gR(HID_ / 128, BN_ / 128);  // (12, 49)

    // ---- exact 4-digit weight decompositions for binary-input GEMMs ----
    split_digits<<<(CC_ + 255) / 256, 256>>>(ap_w,   apd,  CC_);
    split_digits<<<(CC_ + 255) / 256, 256>>>(watt_w, watd, CC_);
    split_digits<<<(CC_ + 255) / 256, 256>>>(wlsm_w, wlsd, CC_);
    split_digits<<<(HC_ + 255) / 256, 256>>>(fc2_w,  fc2d, HC_);
    split_digits<<<(HH_ + 255) / 256, 256>>>(rec_w,  recd, HH_);

    // ---- SSA branch: q/k/v fp32 GEMMs -> 128-step LIF -> attention ----
    sgemm_nt<<<gC, 256>>>(x, q_w, q_b, bq, TBN_, C_, C_);
    sgemm_nt<<<gC, 256>>>(x, k_w, k_b, bk, TBN_, C_, C_);
    sgemm_nt<<<gC, 256>>>(x, v_w, v_b, bv, TBN_, C_, C_);
    lif_seq_i8<<<nb75k, 256>>>(bq, sq, TB_, NC_, NC_, lif_w, 0);
    lif_seq_i8<<<nb75k, 256>>>(bk, sk, TB_, NC_, NC_, lif_w, 1);
    lif_seq_i8<<<nb75k, 256>>>(bv, sv, TB_, NC_, NC_, lif_w, 2);
    attn_kernel<<<TB_ * H_, 256>>>(sq, sk, sv, ab);
    lif_seq_i8<<<nbBNC, 256>>>(ab, abb, T_, BNC_, BNC_, lif_w, 3);
    igemm4_nt<<<gC, 512>>>(abb, apd, ap_b, af, TBN_, C_, C_);
    lif_seq_i8<<<nb75k, 256>>>(af, afb, TB_, NC_, NC_, lif_w, 4);

    // ---- LSM branch ----
    sgemm_nt<<<gH, 256>>>(x, fc1_w, fc1_b, curr, TBN_, HID_, C_);
    lsm_step0<<<nbMH, 256>>>(curr, rec_b, syn, mem, spkb);
    for (int t = 1; t < T_; t++) {
        igemm4_nt<<<gR, 512>>>(spkb + (size_t)(t - 1) * MH_, recd, rec_b, R, BN_, HID_, HID_);
        lsm_step<<<nbMH, 256>>>(curr + (size_t)t * MH_, R, syn, mem,
                                spkb + (size_t)(t - 1) * MH_, spkb + (size_t)t * MH_);
    }
    igemm4_nt<<<gC, 512>>>(spkb, fc2d, fc2_b, l, TBN_, C_, HID_);
    bn_partial<<<98, 384>>>(l, part);
    bn_finalize<<<1, 384>>>(part, stats);
    bn_lif4_i8<<<nbBNC, 256>>>(l, lfb, stats, bnl_g, bnl_b, lif_w, 5);

    // ---- ARIG fusion ----
    igemm4_nt<<<gC, 512>>>(afb, watd, watt_b, ga, TBN_, C_, C_);
    igemm4_nt<<<gC, 512>>>(lfb, wlsd, wlsm_b, gl, TBN_, C_, C_);
    fuse_kernel<<<nbMH, 256>>>(afb, lfb, ga, gl, fu);
    sgemm_nt<<<gC, 256>>>(fu, fp_w, fp_b, o, TBN_, C_, C_);
    bn_partial<<<98, 384>>>(o, part);
    bn_finalize<<<1, 384>>>(part, stats);
    bn_lif4_res<<<nbBNC, 256>>>(o, out, stats, bnf_g, bnf_b, lif_w, 6, x);
}

// round 9
// speedup vs baseline: 1.3429x; 1.3429x over previous
#include <cuda_runtime.h>
#include <math.h>
#include <stdint.h>

// ---------------- problem constants ----------------
#define T_    4
#define B_    32
#define N_    196
#define C_    384
#define H_    8
#define D_    48
#define HID_  1536
#define TB_   128           // T*B
#define NC_   75264         // N*C
#define BNC_  2408448       // B*N*C
#define TBN_  25088         // T*B*N
#define BN_   6272          // B*N
#define MH_   9633792       // BN_*HID_ == TBN_*C_

// ---------------- scratch (device globals; no runtime alloc allowed) ----------------
__device__ float g_bq[MH_];
__device__ float g_bk[MH_];
__device__ float g_bv[MH_];
__device__ float g_ab[MH_];
__device__ float g_af[MH_];
__device__ float g_curr[4 * MH_];
__device__ float g_syn[MH_];
__device__ float g_mem[MH_];
__device__ float g_spk[4 * MH_];
__device__ float g_R[MH_];
__device__ float g_l[MH_];
__device__ float g_ga[MH_];
__device__ float g_gl[MH_];
__device__ float g_fu[MH_];
__device__ float g_o[MH_];
__device__ float g_part[98 * 768];
__device__ float g_stats[768];   // [0:384) mu, [384:768) rstd

// ---------------- f32x2 packed-FMA helpers (sm_100+ PTX; per-lane IEEE fp32 RN) ------
#define FMA2(D, A, B) \
    asm("fma.rn.f32x2 %0, %1, %2, %0;" : "+l"(D) : "l"(A), "l"(B))
#define PACK2(P, X, Y) \
    asm("mov.b64 %0, {%1, %2};" : "=l"(P) : "f"(X), "f"(Y))
#define UNPACK2(X, Y, P) \
    asm("mov.b64 {%0, %1}, %2;" : "=f"(X), "=f"(Y) : "l"(P))

// ================= SGEMM2: C[M,N] = A[M,K] @ W[N,K]^T + bias[N] =================
// Same tiling/loads/order as the round-2 proven sgemm (128x128 tile, BK=8,
// 256 threads, 8x8 acc/thread, double-buffered smem). Inner product uses
// fma.rn.f32x2 — accumulation ORDER per output element is identical to the
// scalar version (one fma per kk, sequential over k), so results are bitwise
// equivalent; only the fma-pipe issue count halves.
#define BM 128
#define BN 128
#define BK 8

__global__ __launch_bounds__(256, 2)
void sgemm_nt(const float* __restrict__ A, const float* __restrict__ W,
              const float* __restrict__ bias, float* __restrict__ C,
              int M, int N, int K) {
    __shared__ float As[2][BK][BM];
    __shared__ float Bs[2][BK][BN];

    const int tid = threadIdx.x;
    const int bm = blockIdx.y * BM;
    const int bn = blockIdx.x * BN;

    // global load mapping: each thread loads one float4 of A and one of W per k-tile
    const int lr = tid >> 1;            // 0..127 (row within tile)
    const int lc = (tid & 1) * 4;       // 0 or 4 (k offset)
    const float* Ap = A + (size_t)(bm + lr) * K + lc;
    const float* Wp = W + (size_t)(bn + lr) * K + lc;

    // compute mapping
    const int tx = tid & 15;            // 0..15
    const int ty = tid >> 4;            // 0..15

    // accumulators: 8 rows x 4 column-pairs, packed f32x2
    unsigned long long accp[8][4];
#pragma unroll
    for (int i = 0; i < 8; i++)
#pragma unroll
        for (int jp = 0; jp < 4; jp++) accp[i][jp] = 0ull;

    // prologue: load k-tile 0 into buffer 0
    float4 av = *(const float4*)Ap;
    float4 wv = *(const float4*)Wp;
    As[0][lc + 0][lr] = av.x; As[0][lc + 1][lr] = av.y;
    As[0][lc + 2][lr] = av.z; As[0][lc + 3][lr] = av.w;
    Bs[0][lc + 0][lr] = wv.x; Bs[0][lc + 1][lr] = wv.y;
    Bs[0][lc + 2][lr] = wv.z; Bs[0][lc + 3][lr] = wv.w;
    __syncthreads();

    const int nk = K / BK;
    for (int kt = 0; kt < nk; kt++) {
        const int cur = kt & 1;
        if (kt + 1 < nk) {
            av = *(const float4*)(Ap + (size_t)(kt + 1) * BK);
            wv = *(const float4*)(Wp + (size_t)(kt + 1) * BK);
        }
#pragma unroll
        for (int kk = 0; kk < BK; kk++) {
            float4 a0 = *(const float4*)&As[cur][kk][ty * 4];
            float4 a1 = *(const float4*)&As[cur][kk][ty * 4 + 64];
            float4 b0 = *(const float4*)&Bs[cur][kk][tx * 4];
            float4 b1 = *(const float4*)&Bs[cur][kk][tx * 4 + 64];
            unsigned long long bp[4];
            PACK2(bp[0], b0.x, b0.y);
            PACK2(bp[1], b0.z, b0.w);
            PACK2(bp[2], b1.x, b1.y);
            PACK2(bp[3], b1.z, b1.w);
            float avs[8] = {a0.x, a0.y, a0.z, a0.w, a1.x, a1.y, a1.z, a1.w};
#pragma unroll
            for (int i = 0; i < 8; i++) {
                unsigned long long ap;
                PACK2(ap, avs[i], avs[i]);
                FMA2(accp[i][0], ap, bp[0]);
                FMA2(accp[i][1], ap, bp[1]);
                FMA2(accp[i][2], ap, bp[2]);
                FMA2(accp[i][3], ap, bp[3]);
            }
        }
        if (kt + 1 < nk) {
            const int nxt = cur ^ 1;
            As[nxt][lc + 0][lr] = av.x; As[nxt][lc + 1][lr] = av.y;
            As[nxt][lc + 2][lr] = av.z; As[nxt][lc + 3][lr] = av.w;
            Bs[nxt][lc + 0][lr] = wv.x; Bs[nxt][lc + 1][lr] = wv.y;
            Bs[nxt][lc + 2][lr] = wv.z; Bs[nxt][lc + 3][lr] = wv.w;
            __syncthreads();
        }
    }

    // epilogue: unpack, add bias, vectorized stores (same addresses as round-2)
#pragma unroll
    for (int i = 0; i < 8; i++) {
        const int row = bm + ty * 4 + (i & 3) + ((i >> 2) << 6);
#pragma unroll
        for (int jb = 0; jb < 2; jb++) {
            const int col = bn + tx * 4 + jb * 64;
            float4 bv4 = *(const float4*)&bias[col];
            float c0, c1, c2, c3;
            UNPACK2(c0, c1, accp[i][jb * 2 + 0]);
            UNPACK2(c2, c3, accp[i][jb * 2 + 1]);
            float4 v;
            v.x = c0 + bv4.x;
            v.y = c1 + bv4.y;
            v.z = c2 + bv4.z;
            v.w = c3 + bv4.w;
            *(float4*)&C[(size_t)row * N + col] = v;
        }
    }
}

// ---------------- LIF scan (in-place), depth-4 prefetch pipeline ----------------
__global__ void lif_seq(float* __restrict__ buf, int steps, long stride, long nelem,
                        const float* __restrict__ lif_w, int widx) {
    long idx = (long)blockIdx.x * blockDim.x + threadIdx.x;
    if (idx >= nelem) return;
    const float decay = 1.0f / (1.0f + expf(-lif_w[widx]));
    float v = 0.0f;
    float xs[4];
#pragma unroll
    for (int t = 0; t < 4; t++)
        if (t < steps) xs[t] = buf[(long)t * stride + idx];
    for (int t = 0; t < steps; t++) {
        float x = xs[t & 3];
        if (t + 4 < steps) xs[t & 3] = buf[(long)(t + 4) * stride + idx];
        v = v + (x - v) * decay;
        float s = (v >= 1.0f) ? 1.0f : 0.0f;
        buf[(long)t * stride + idx] = s;
        v *= (1.0f - s);
    }
}

// ---------------- spiking attention, one block per (t*B+b, h) ----------------
__global__ __launch_bounds__(256)
void attn_kernel(const float* __restrict__ sq, const float* __restrict__ sk,
                 const float* __restrict__ sv, float* __restrict__ abuf) {
    const int tb = blockIdx.x >> 3;
    const int h = blockIdx.x & 7;
    __shared__ unsigned long long qb[N_], kb[N_], vb[N_];
    __shared__ unsigned char cnt[N_ * 200];
    const int tid = threadIdx.x;

    for (int i = tid; i < N_; i += 256) { qb[i] = 0ull; kb[i] = 0ull; vb[i] = 0ull; }
    __syncthreads();

    const long base = (long)tb * NC_ + h * D_;
    for (int e = tid; e < N_ * D_; e += 256) {
        int n = e / D_, d = e % D_;
        long off = base + (long)n * C_ + d;
        unsigned long long bit = 1ull << d;
        if (sq[off] != 0.0f) atomicOr(&qb[n], bit);
        if (sk[off] != 0.0f) atomicOr(&kb[n], bit);
        if (sv[off] != 0.0f) atomicOr(&vb[n], bit);
    }
    __syncthreads();

    for (int i = tid; i < N_ * N_; i += 256) {
        int n = i / N_, m = i - n * N_;
        cnt[n * 200 + m] = (unsigned char)__popcll(qb[n] & kb[m]);
    }
    __syncthreads();

    const float scale = 0.14433756729740643f;  // 48^-0.5
    for (int o = tid; o < N_ * D_; o += 256) {
        int n = o / D_, d = o - n * D_;
        const unsigned char* crow = &cnt[n * 200];
        int acc = 0;
#pragma unroll 4
        for (int m = 0; m < N_; m++)
            acc += (int)crow[m] * (int)((vb[m] >> d) & 1ull);
        abuf[(long)tb * NC_ + h * (D_ * N_) + d * N_ + n] = scale * (float)acc;
    }
}

// ---------------- LSM (RSynaptic) elementwise steps ----------------
__global__ void lsm_step0(const float* __restrict__ curr, const float* __restrict__ rec_b,
                          float* __restrict__ syn, float* __restrict__ mem,
                          float* __restrict__ spk) {
    long idx = (long)blockIdx.x * blockDim.x + threadIdx.x;
    if (idx >= (long)MH_) return;
    int hc = (int)(idx % HID_);
    float s = curr[idx] + rec_b[hc];
    syn[idx] = s;
    mem[idx] = s;
    spk[idx] = (s - 1.0f >= 0.0f) ? 1.0f : 0.0f;
}

__global__ void lsm_step(const float* __restrict__ curr_t, const float* __restrict__ R,
                         float* __restrict__ syn, float* __restrict__ mem,
                         const float* __restrict__ spk_prev, float* __restrict__ spk_out) {
    long idx = (long)blockIdx.x * blockDim.x + threadIdx.x;
    if (idx >= (long)MH_) return;
    float sp = spk_prev[idx];
    float s = 0.9f * syn[idx] + curr_t[idx] + R[idx];
    float m = 0.8f * mem[idx] + s - sp * 1.0f;
    syn[idx] = s;
    mem[idx] = m;
    spk_out[idx] = (m - 1.0f >= 0.0f) ? 1.0f : 0.0f;
}

// ---------------- BatchNorm stats (deterministic 2-stage) ----------------
__global__ void bn_partial(const float* __restrict__ X, float* __restrict__ part) {
    int c = threadIdx.x;
    long r0 = (long)blockIdx.x * 256;
    float s = 0.0f, s2 = 0.0f;
    for (int r = 0; r < 256; r++) {
        float v = X[(r0 + r) * C_ + c];
        s += v;
        s2 += v * v;
    }
    part[blockIdx.x * 768 + c] = s;
    part[blockIdx.x * 768 + 384 + c] = s2;
}

__global__ void bn_finalize(const float* __restrict__ part, float* __restrict__ stats) {
    int c = threadIdx.x;
    float s = 0.0f, s2 = 0.0f;
    for (int p = 0; p < 98; p++) {
        s += part[p * 768 + c];
        s2 += part[p * 768 + 384 + c];
    }
    const float inv = 1.0f / 25088.0f;
    float m = s * inv;
    float var = s2 * inv - m * m;
    stats[c] = m;
    stats[384 + c] = 1.0f / sqrtf(var + 1e-5f);
}

// ---------------- fused BN-apply + 4-step LIF (+ optional residual into d_out) -------
__global__ void bn_lif4(const float* __restrict__ lin, float* __restrict__ out,
                        const float* __restrict__ stats,
                        const float* __restrict__ gamma, const float* __restrict__ beta,
                        const float* __restrict__ lif_w, int widx,
                        const float* __restrict__ xadd) {
    long idx = (long)blockIdx.x * blockDim.x + threadIdx.x;
    if (idx >= (long)BNC_) return;
    int c = (int)(idx % C_);
    float mu = stats[c], rstd = stats[384 + c];
    float gg = gamma[c], bb = beta[c];
    float decay = 1.0f / (1.0f + expf(-lif_w[widx]));
    float v = 0.0f;
    float xs[4];
#pragma unroll
    for (int t = 0; t < 4; t++) xs[t] = lin[(long)t * BNC_ + idx];
#pragma unroll
    for (int t = 0; t < 4; t++) {
        long o = (long)t * BNC_ + idx;
        float xv = (xs[t] - mu) * rstd * gg + bb;
        v = v + (xv - v) * decay;
        float s = (v >= 1.0f) ? 1.0f : 0.0f;
        v *= (1.0f - s);
        if (xadd) out[o] = xadd[o] + s;
        else      out[o] = s;
    }
}

// ---------------- ARIG fusion elementwise ----------------
__global__ void fuse_kernel(const float* __restrict__ af, const float* __restrict__ lf,
                            const float* __restrict__ ga, const float* __restrict__ gl,
                            float* __restrict__ fu) {
    long idx = (long)blockIdx.x * blockDim.x + threadIdx.x;
    if (idx >= (long)MH_) return;
    float gate_attn = 1.0f / (1.0f + expf(-gl[idx]));
    float gate_lsm  = 1.0f / (1.0f + expf(-ga[idx]));
    fu[idx] = af[idx] * gate_attn + lf[idx] * gate_lsm;
}

// ---------------- launch ----------------
extern "C" void kernel_launch(void* const* d_in, const int* in_sizes, int n_in,
                              void* d_out, int out_size) {
    const float* x      = (const float*)d_in[0];
    const float* q_w    = (const float*)d_in[1];
    const float* q_b    = (const float*)d_in[2];
    const float* k_w    = (const float*)d_in[3];
    const float* k_b    = (const float*)d_in[4];
    const float* v_w    = (const float*)d_in[5];
    const float* v_b    = (const float*)d_in[6];
    const float* ap_w   = (const float*)d_in[7];
    const float* ap_b   = (const float*)d_in[8];
    const float* fc1_w  = (const float*)d_in[9];
    const float* fc1_b  = (const float*)d_in[10];
    const float* rec_w  = (const float*)d_in[11];
    const float* rec_b  = (const float*)d_in[12];
    const float* fc2_w  = (const float*)d_in[13];
    const float* fc2_b  = (const float*)d_in[14];
    const float* bnl_g  = (const float*)d_in[15];
    const float* bnl_b  = (const float*)d_in[16];
    const float* watt_w = (const float*)d_in[17];
    const float* watt_b = (const float*)d_in[18];
    const float* wlsm_w = (const float*)d_in[19];
    const float* wlsm_b = (const float*)d_in[20];
    const float* fp_w   = (const float*)d_in[21];
    const float* fp_b   = (const float*)d_in[22];
    const float* bnf_g  = (const float*)d_in[23];
    const float* bnf_b  = (const float*)d_in[24];
    const float* lif_w  = (const float*)d_in[25];
    float* out = (float*)d_out;

    float *bq, *bk, *bv, *ab, *af, *curr, *syn, *mem, *spk, *R, *l, *ga, *gl, *fu, *o, *part, *stats;
    cudaGetSymbolAddress((void**)&bq, g_bq);
    cudaGetSymbolAddress((void**)&bk, g_bk);
    cudaGetSymbolAddress((void**)&bv, g_bv);
    cudaGetSymbolAddress((void**)&ab, g_ab);
    cudaGetSymbolAddress((void**)&af, g_af);
    cudaGetSymbolAddress((void**)&curr, g_curr);
    cudaGetSymbolAddress((void**)&syn, g_syn);
    cudaGetSymbolAddress((void**)&mem, g_mem);
    cudaGetSymbolAddress((void**)&spk, g_spk);
    cudaGetSymbolAddress((void**)&R, g_R);
    cudaGetSymbolAddress((void**)&l, g_l);
    cudaGetSymbolAddress((void**)&ga, g_ga);
    cudaGetSymbolAddress((void**)&gl, g_gl);
    cudaGetSymbolAddress((void**)&fu, g_fu);
    cudaGetSymbolAddress((void**)&o, g_o);
    cudaGetSymbolAddress((void**)&part, g_part);
    cudaGetSymbolAddress((void**)&stats, g_stats);

    const dim3 gC(C_ / BN, TBN_ / BM);     // (3, 196)
    const dim3 gH(HID_ / BN, TBN_ / BM);   // (12, 196) fc1
    const dim3 gR(HID_ / BN, BN_ / BM);    // (12, 49)  rec
    const int nb75k = (NC_ + 255) / 256;
    const int nbBNC = (BNC_ + 255) / 256;
    const int nbMH  = (MH_ + 255) / 256;

    // --- SSA branch ---
    sgemm_nt<<<gC, 256>>>(x, q_w, q_b, bq, TBN_, C_, C_);
    sgemm_nt<<<gC, 256>>>(x, k_w, k_b, bk, TBN_, C_, C_);
    sgemm_nt<<<gC, 256>>>(x, v_w, v_b, bv, TBN_, C_, C_);
    lif_seq<<<nb75k, 256>>>(bq, TB_, NC_, NC_, lif_w, 0);
    lif_seq<<<nb75k, 256>>>(bk, TB_, NC_, NC_, lif_w, 1);
    lif_seq<<<nb75k, 256>>>(bv, TB_, NC_, NC_, lif_w, 2);

    attn_kernel<<<TB_ * H_, 256>>>(bq, bk, bv, ab);
    lif_seq<<<nbBNC, 256>>>(ab, T_, BNC_, BNC_, lif_w, 3);

    sgemm_nt<<<gC, 256>>>(ab, ap_w, ap_b, af, TBN_, C_, C_);
    lif_seq<<<nb75k, 256>>>(af, TB_, NC_, NC_, lif_w, 4);

    // --- LSM branch ---
    sgemm_nt<<<gH, 256>>>(x, fc1_w, fc1_b, curr, TBN_, HID_, C_);
    lsm_step0<<<nbMH, 256>>>(curr, rec_b, syn, mem, spk);
    for (int t = 1; t < T_; t++) {
        sgemm_nt<<<gR, 256>>>(spk + (size_t)(t - 1) * MH_, rec_w, rec_b, R, BN_, HID_, HID_);
        lsm_step<<<nbMH, 256>>>(curr + (size_t)t * MH_, R, syn, mem,
                                spk + (size_t)(t - 1) * MH_, spk + (size_t)t * MH_);
    }
    sgemm_nt<<<gC, 256>>>(spk, fc2_w, fc2_b, l, TBN_, C_, HID_);
    bn_partial<<<98, 384>>>(l, part);
    bn_finalize<<<1, 384>>>(part, stats);
    bn_lif4<<<nbBNC, 256>>>(l, l, stats, bnl_g, bnl_b, lif_w, 5, nullptr);

    // --- ARIG fusion ---
    sgemm_nt<<<gC, 256>>>(af, watt_w, watt_b, ga, TBN_, C_, C_);
    sgemm_nt<<<gC, 256>>>(l,  wlsm_w, wlsm_b, gl, TBN_, C_, C_);
    fuse_kernel<<<nbMH, 256>>>(af, l, ga, gl, fu);
    sgemm_nt<<<gC, 256>>>(fu, fp_w, fp_b, o, TBN_, C_, C_);
    bn_partial<<<98, 384>>>(o, part);
    bn_finalize<<<1, 384>>>(part, stats);
    bn_lif4<<<nbBNC, 256>>>(o, out, stats, bnf_g, bnf_b, lif_w, 6, x);
}

// round 10
// speedup vs baseline: 1.5926x; 1.1860x over previous
#include <cuda_runtime.h>
#include <math.h>
#include <stdint.h>

// ---------------- problem constants ----------------
#define T_    4
#define B_    32
#define N_    196
#define C_    384
#define H_    8
#define D_    48
#define HID_  1536
#define TB_   128           // T*B
#define NC_   75264         // N*C
#define BNC_  2408448       // B*N*C
#define TBN_  25088         // T*B*N
#define BN_   6272          // B*N
#define MH_   9633792       // BN_*HID_ == TBN_*C_
#define CC_   (C_ * C_)
#define HH_   (HID_ * HID_)

// ---------------- scratch (device globals; no runtime alloc allowed) ----------------
__device__ float g_bq[MH_];
__device__ float g_bk[MH_];
__device__ float g_bv[MH_];
__device__ float g_ab[MH_];
__device__ float g_af[MH_];
__device__ float g_curr[4 * MH_];
__device__ float g_syn[MH_];
__device__ float g_mem[MH_];
__device__ float g_spk[4 * MH_];
__device__ float g_R[MH_];
__device__ float g_l[MH_];
__device__ float g_ga[MH_];
__device__ float g_gl[MH_];
__device__ float g_fu[MH_];
__device__ float g_o[MH_];
__device__ float g_part[98 * 768];
__device__ float g_stats[768];   // [0:384) mu, [384:768) rstd
// transposed weights for gather-SpMM
__device__ float g_apT[CC_];
__device__ float g_watT[CC_];
__device__ float g_wlsT[CC_];
__device__ float g_recT[HH_];

// ---------------- f32x2 packed-FMA helpers ----------------
#define FMA2(D, A, B) \
    asm("fma.rn.f32x2 %0, %1, %2, %0;" : "+l"(D) : "l"(A), "l"(B))
#define PACK2(P, X, Y) \
    asm("mov.b64 %0, {%1, %2};" : "=l"(P) : "f"(X), "f"(Y))
#define UNPACK2(X, Y, P) \
    asm("mov.b64 {%0, %1}, %2;" : "=f"(X), "=f"(Y) : "l"(P))

// ================= SGEMM2 (round-9 proven, unchanged) =================
#define BM 128
#define BN 128
#define BK 8

__global__ __launch_bounds__(256, 2)
void sgemm_nt(const float* __restrict__ A, const float* __restrict__ W,
              const float* __restrict__ bias, float* __restrict__ C,
              int M, int N, int K) {
    __shared__ float As[2][BK][BM];
    __shared__ float Bs[2][BK][BN];

    const int tid = threadIdx.x;
    const int bm = blockIdx.y * BM;
    const int bn = blockIdx.x * BN;

    const int lr = tid >> 1;
    const int lc = (tid & 1) * 4;
    const float* Ap = A + (size_t)(bm + lr) * K + lc;
    const float* Wp = W + (size_t)(bn + lr) * K + lc;

    const int tx = tid & 15;
    const int ty = tid >> 4;

    unsigned long long accp[8][4];
#pragma unroll
    for (int i = 0; i < 8; i++)
#pragma unroll
        for (int jp = 0; jp < 4; jp++) accp[i][jp] = 0ull;

    float4 av = *(const float4*)Ap;
    float4 wv = *(const float4*)Wp;
    As[0][lc + 0][lr] = av.x; As[0][lc + 1][lr] = av.y;
    As[0][lc + 2][lr] = av.z; As[0][lc + 3][lr] = av.w;
    Bs[0][lc + 0][lr] = wv.x; Bs[0][lc + 1][lr] = wv.y;
    Bs[0][lc + 2][lr] = wv.z; Bs[0][lc + 3][lr] = wv.w;
    __syncthreads();

    const int nk = K / BK;
    for (int kt = 0; kt < nk; kt++) {
        const int cur = kt & 1;
        if (kt + 1 < nk) {
            av = *(const float4*)(Ap + (size_t)(kt + 1) * BK);
            wv = *(const float4*)(Wp + (size_t)(kt + 1) * BK);
        }
#pragma unroll
        for (int kk = 0; kk < BK; kk++) {
            float4 a0 = *(const float4*)&As[cur][kk][ty * 4];
            float4 a1 = *(const float4*)&As[cur][kk][ty * 4 + 64];
            float4 b0 = *(const float4*)&Bs[cur][kk][tx * 4];
            float4 b1 = *(const float4*)&Bs[cur][kk][tx * 4 + 64];
            unsigned long long bp[4];
            PACK2(bp[0], b0.x, b0.y);
            PACK2(bp[1], b0.z, b0.w);
            PACK2(bp[2], b1.x, b1.y);
            PACK2(bp[3], b1.z, b1.w);
            float avs[8] = {a0.x, a0.y, a0.z, a0.w, a1.x, a1.y, a1.z, a1.w};
#pragma unroll
            for (int i = 0; i < 8; i++) {
                unsigned long long ap;
                PACK2(ap, avs[i], avs[i]);
                FMA2(accp[i][0], ap, bp[0]);
                FMA2(accp[i][1], ap, bp[1]);
                FMA2(accp[i][2], ap, bp[2]);
                FMA2(accp[i][3], ap, bp[3]);
            }
        }
        if (kt + 1 < nk) {
            const int nxt = cur ^ 1;
            As[nxt][lc + 0][lr] = av.x; As[nxt][lc + 1][lr] = av.y;
            As[nxt][lc + 2][lr] = av.z; As[nxt][lc + 3][lr] = av.w;
            Bs[nxt][lc + 0][lr] = wv.x; Bs[nxt][lc + 1][lr] = wv.y;
            Bs[nxt][lc + 2][lr] = wv.z; Bs[nxt][lc + 3][lr] = wv.w;
            __syncthreads();
        }
    }

#pragma unroll
    for (int i = 0; i < 8; i++) {
        const int row = bm + ty * 4 + (i & 3) + ((i >> 2) << 6);
#pragma unroll
        for (int jb = 0; jb < 2; jb++) {
            const int col = bn + tx * 4 + jb * 64;
            float4 bv4 = *(const float4*)&bias[col];
            float c0, c1, c2, c3;
            UNPACK2(c0, c1, accp[i][jb * 2 + 0]);
            UNPACK2(c2, c3, accp[i][jb * 2 + 1]);
            float4 v;
            v.x = c0 + bv4.x;
            v.y = c1 + bv4.y;
            v.z = c2 + bv4.z;
            v.w = c3 + bv4.w;
            *(float4*)&C[(size_t)row * N + col] = v;
        }
    }
}

// ================= gather-SpMM: C[m,:] = bias + sum_{k: A[m,k]!=0} WT[k,:] =================
// A[M,K] binary spikes (float 0/1); WT[K,N] row-major (transposed weight).
// One block per row m, 256 threads, NV outputs/thread. Deterministic:
// ballot-compaction (warp w owns 32-chunks w, w+8, ...), fixed accumulation order.
// Skipping exact zeros is bitwise identical to summing them.
template<int NV>
__global__ __launch_bounds__(256)
void spmm_gather(const float* __restrict__ A, const float* __restrict__ WT,
                 const float* __restrict__ bias, float* __restrict__ C,
                 int N, int K) {
    __shared__ short idxs[1536];
    __shared__ int wcnt[8];
    __shared__ int woff[8];
    __shared__ int s_nact;

    const int m = blockIdx.x;
    const int tid = threadIdx.x;
    const int lane = tid & 31;
    const int wid = tid >> 5;
    const float* arow = A + (size_t)m * K;
    const int nch = K >> 5;

    // pass 1: per-warp counts
    int cnt = 0;
    for (int c = wid; c < nch; c += 8) {
        unsigned mask = __ballot_sync(0xffffffffu, arow[c * 32 + lane] != 0.0f);
        cnt += __popc(mask);
    }
    if (lane == 0) wcnt[wid] = cnt;
    __syncthreads();
    if (tid == 0) {
        int tot = 0;
#pragma unroll
        for (int w = 0; w < 8; w++) { woff[w] = tot; tot += wcnt[w]; }
        s_nact = tot;
    }
    __syncthreads();

    // pass 2: write indices (deterministic order)
    int base = woff[wid];
    for (int c = wid; c < nch; c += 8) {
        int k = c * 32 + lane;
        bool act = (arow[k] != 0.0f);
        unsigned mask = __ballot_sync(0xffffffffu, act);
        if (act) idxs[base + __popc(mask & ((1u << lane) - 1u))] = (short)k;
        base += __popc(mask);
    }
    __syncthreads();

    const int nact = s_nact;
    float acc[NV];
#pragma unroll
    for (int v = 0; v < NV; v++) {
        int n = tid + v * 256;
        acc[v] = (n < N) ? bias[n] : 0.0f;
    }

    int i = 0;
    for (; i + 2 <= nact; i += 2) {
        const float* w0 = WT + (size_t)idxs[i] * N;
        const float* w1 = WT + (size_t)idxs[i + 1] * N;
        float r0[NV], r1[NV];
#pragma unroll
        for (int v = 0; v < NV; v++) {
            int n = tid + v * 256;
            if (n < N) { r0[v] = w0[n]; r1[v] = w1[n]; }
        }
#pragma unroll
        for (int v = 0; v < NV; v++) {
            int n = tid + v * 256;
            if (n < N) { acc[v] += r0[v]; acc[v] += r1[v]; }
        }
    }
    if (i < nact) {
        const float* w0 = WT + (size_t)idxs[i] * N;
#pragma unroll
        for (int v = 0; v < NV; v++) {
            int n = tid + v * 256;
            if (n < N) acc[v] += w0[n];
        }
    }

#pragma unroll
    for (int v = 0; v < NV; v++) {
        int n = tid + v * 256;
        if (n < N) C[(size_t)m * N + n] = acc[v];
    }
}

// ---------------- transpose W[Nw,Kw] -> WT[Kw,Nw] ----------------
__global__ void transpose_k(const float* __restrict__ W, float* __restrict__ WT,
                            int Nw, int Kw) {
    __shared__ float t[32][33];
    int bx = blockIdx.x * 32, by = blockIdx.y * 32;
    int x = bx + threadIdx.x;
#pragma unroll
    for (int j = 0; j < 32; j += 8) {
        int y = by + threadIdx.y + j;
        if (y < Nw && x < Kw) t[threadIdx.y + j][threadIdx.x] = W[(size_t)y * Kw + x];
    }
    __syncthreads();
    int x2 = by + threadIdx.x;
#pragma unroll
    for (int j = 0; j < 32; j += 8) {
        int y2 = bx + threadIdx.y + j;
        if (y2 < Kw && x2 < Nw) WT[(size_t)y2 * Nw + x2] = t[threadIdx.x][threadIdx.y + j];
    }
}

// ---------------- LIF scan (in-place), depth-4 prefetch ----------------
__global__ void lif_seq(float* __restrict__ buf, int steps, long stride, long nelem,
                        const float* __restrict__ lif_w, int widx) {
    long idx = (long)blockIdx.x * blockDim.x + threadIdx.x;
    if (idx >= nelem) return;
    const float decay = 1.0f / (1.0f + expf(-lif_w[widx]));
    float v = 0.0f;
    float xs[4];
#pragma unroll
    for (int t = 0; t < 4; t++)
        if (t < steps) xs[t] = buf[(long)t * stride + idx];
    for (int t = 0; t < steps; t++) {
        float x = xs[t & 3];
        if (t + 4 < steps) xs[t & 3] = buf[(long)(t + 4) * stride + idx];
        v = v + (x - v) * decay;
        float s = (v >= 1.0f) ? 1.0f : 0.0f;
        buf[(long)t * stride + idx] = s;
        v *= (1.0f - s);
    }
}

// ---------------- merged q/k/v LIF: blockIdx.y selects buffer/widx ----------------
__global__ void lif_seq3(float* __restrict__ b0, float* __restrict__ b1,
                         float* __restrict__ b2, const float* __restrict__ lif_w) {
    long idx = (long)blockIdx.x * blockDim.x + threadIdx.x;
    if (idx >= (long)NC_) return;
    const int which = blockIdx.y;
    float* buf = (which == 0) ? b0 : ((which == 1) ? b1 : b2);
    const float decay = 1.0f / (1.0f + expf(-lif_w[which]));
    float v = 0.0f;
    float xs[4];
#pragma unroll
    for (int t = 0; t < 4; t++) xs[t] = buf[(long)t * NC_ + idx];
    for (int t = 0; t < TB_; t++) {
        float x = xs[t & 3];
        if (t + 4 < TB_) xs[t & 3] = buf[(long)(t + 4) * NC_ + idx];
        v = v + (x - v) * decay;
        float s = (v >= 1.0f) ? 1.0f : 0.0f;
        buf[(long)t * NC_ + idx] = s;
        v *= (1.0f - s);
    }
}

// ---------------- spiking attention, one block per (t*B+b, h) ----------------
__global__ __launch_bounds__(256)
void attn_kernel(const float* __restrict__ sq, const float* __restrict__ sk,
                 const float* __restrict__ sv, float* __restrict__ abuf) {
    const int tb = blockIdx.x >> 3;
    const int h = blockIdx.x & 7;
    __shared__ unsigned long long qb[N_], kb[N_], vb[N_];
    __shared__ unsigned char cnt[N_ * 200];
    const int tid = threadIdx.x;

    for (int i = tid; i < N_; i += 256) { qb[i] = 0ull; kb[i] = 0ull; vb[i] = 0ull; }
    __syncthreads();

    const long base = (long)tb * NC_ + h * D_;
    for (int e = tid; e < N_ * D_; e += 256) {
        int n = e / D_, d = e % D_;
        long off = base + (long)n * C_ + d;
        unsigned long long bit = 1ull << d;
        if (sq[off] != 0.0f) atomicOr(&qb[n], bit);
        if (sk[off] != 0.0f) atomicOr(&kb[n], bit);
        if (sv[off] != 0.0f) atomicOr(&vb[n], bit);
    }
    __syncthreads();

    for (int i = tid; i < N_ * N_; i += 256) {
        int n = i / N_, m = i - n * N_;
        cnt[n * 200 + m] = (unsigned char)__popcll(qb[n] & kb[m]);
    }
    __syncthreads();

    const float scale = 0.14433756729740643f;  // 48^-0.5
    for (int o = tid; o < N_ * D_; o += 256) {
        int n = o / D_, d = o - n * D_;
        const unsigned char* crow = &cnt[n * 200];
        int acc = 0;
#pragma unroll 4
        for (int m = 0; m < N_; m++)
            acc += (int)crow[m] * (int)((vb[m] >> d) & 1ull);
        abuf[(long)tb * NC_ + h * (D_ * N_) + d * N_ + n] = scale * (float)acc;
    }
}

// ---------------- LSM (RSynaptic) elementwise steps ----------------
__global__ void lsm_step0(const float* __restrict__ curr, const float* __restrict__ rec_b,
                          float* __restrict__ syn, float* __restrict__ mem,
                          float* __restrict__ spk) {
    long idx = (long)blockIdx.x * blockDim.x + threadIdx.x;
    if (idx >= (long)MH_) return;
    int hc = (int)(idx % HID_);
    float s = curr[idx] + rec_b[hc];
    syn[idx] = s;
    mem[idx] = s;
    spk[idx] = (s - 1.0f >= 0.0f) ? 1.0f : 0.0f;
}

__global__ void lsm_step(const float* __restrict__ curr_t, const float* __restrict__ R,
                         float* __restrict__ syn, float* __restrict__ mem,
                         const float* __restrict__ spk_prev, float* __restrict__ spk_out) {
    long idx = (long)blockIdx.x * blockDim.x + threadIdx.x;
    if (idx >= (long)MH_) return;
    float sp = spk_prev[idx];
    float s = 0.9f * syn[idx] + curr_t[idx] + R[idx];
    float m = 0.8f * mem[idx] + s - sp * 1.0f;
    syn[idx] = s;
    mem[idx] = m;
    spk_out[idx] = (m - 1.0f >= 0.0f) ? 1.0f : 0.0f;
}

// ---------------- BatchNorm stats (deterministic 2-stage) ----------------
__global__ void bn_partial(const float* __restrict__ X, float* __restrict__ part) {
    int c = threadIdx.x;
    long r0 = (long)blockIdx.x * 256;
    float s = 0.0f, s2 = 0.0f;
    for (int r = 0; r < 256; r++) {
        float v = X[(r0 + r) * C_ + c];
        s += v;
        s2 += v * v;
    }
    part[blockIdx.x * 768 + c] = s;
    part[blockIdx.x * 768 + 384 + c] = s2;
}

__global__ void bn_finalize(const float* __restrict__ part, float* __restrict__ stats) {
    int c = threadIdx.x;
    float s = 0.0f, s2 = 0.0f;
    for (int p = 0; p < 98; p++) {
        s += part[p * 768 + c];
        s2 += part[p * 768 + 384 + c];
    }
    const float inv = 1.0f / 25088.0f;
    float m = s * inv;
    float var = s2 * inv - m * m;
    stats[c] = m;
    stats[384 + c] = 1.0f / sqrtf(var + 1e-5f);
}

// ---------------- fused BN-apply + 4-step LIF (+ optional residual) ----------------
__global__ void bn_lif4(const float* __restrict__ lin, float* __restrict__ out,
                        const float* __restrict__ stats,
                        const float* __restrict__ gamma, const float* __restrict__ beta,
                        const float* __restrict__ lif_w, int widx,
                        const float* __restrict__ xadd) {
    long idx = (long)blockIdx.x * blockDim.x + threadIdx.x;
    if (idx >= (long)BNC_) return;
    int c = (int)(idx % C_);
    float mu = stats[c], rstd = stats[384 + c];
    float gg = gamma[c], bb = beta[c];
    float decay = 1.0f / (1.0f + expf(-lif_w[widx]));
    float v = 0.0f;
    float xs[4];
#pragma unroll
    for (int t = 0; t < 4; t++) xs[t] = lin[(long)t * BNC_ + idx];
#pragma unroll
    for (int t = 0; t < 4; t++) {
        long o = (long)t * BNC_ + idx;
        float xv = (xs[t] - mu) * rstd * gg + bb;
        v = v + (xv - v) * decay;
        float s = (v >= 1.0f) ? 1.0f : 0.0f;
        v *= (1.0f - s);
        if (xadd) out[o] = xadd[o] + s;
        else      out[o] = s;
    }
}

// ---------------- ARIG fusion elementwise ----------------
__global__ void fuse_kernel(const float* __restrict__ af, const float* __restrict__ lf,
                            const float* __restrict__ ga, const float* __restrict__ gl,
                            float* __restrict__ fu) {
    long idx = (long)blockIdx.x * blockDim.x + threadIdx.x;
    if (idx >= (long)MH_) return;
    float gate_attn = 1.0f / (1.0f + expf(-gl[idx]));
    float gate_lsm  = 1.0f / (1.0f + expf(-ga[idx]));
    fu[idx] = af[idx] * gate_attn + lf[idx] * gate_lsm;
}

// ---------------- launch ----------------
extern "C" void kernel_launch(void* const* d_in, const int* in_sizes, int n_in,
                              void* d_out, int out_size) {
    const float* x      = (const float*)d_in[0];
    const float* q_w    = (const float*)d_in[1];
    const float* q_b    = (const float*)d_in[2];
    const float* k_w    = (const float*)d_in[3];
    const float* k_b    = (const float*)d_in[4];
    const float* v_w    = (const float*)d_in[5];
    const float* v_b    = (const float*)d_in[6];
    const float* ap_w   = (const float*)d_in[7];
    const float* ap_b   = (const float*)d_in[8];
    const float* fc1_w  = (const float*)d_in[9];
    const float* fc1_b  = (const float*)d_in[10];
    const float* rec_w  = (const float*)d_in[11];
    const float* rec_b  = (const float*)d_in[12];
    const float* fc2_w  = (const float*)d_in[13];
    const float* fc2_b  = (const float*)d_in[14];
    const float* bnl_g  = (const float*)d_in[15];
    const float* bnl_b  = (const float*)d_in[16];
    const float* watt_w = (const float*)d_in[17];
    const float* watt_b = (const float*)d_in[18];
    const float* wlsm_w = (const float*)d_in[19];
    const float* wlsm_b = (const float*)d_in[20];
    const float* fp_w   = (const float*)d_in[21];
    const float* fp_b   = (const float*)d_in[22];
    const float* bnf_g  = (const float*)d_in[23];
    const float* bnf_b  = (const float*)d_in[24];
    const float* lif_w  = (const float*)d_in[25];
    float* out = (float*)d_out;

    float *bq, *bk, *bv, *ab, *af, *curr, *syn, *mem, *spk, *R, *l, *ga, *gl, *fu, *o, *part, *stats;
    float *apT, *watT, *wlsT, *recT;
    cudaGetSymbolAddress((void**)&bq, g_bq);
    cudaGetSymbolAddress((void**)&bk, g_bk);
    cudaGetSymbolAddress((void**)&bv, g_bv);
    cudaGetSymbolAddress((void**)&ab, g_ab);
    cudaGetSymbolAddress((void**)&af, g_af);
    cudaGetSymbolAddress((void**)&curr, g_curr);
    cudaGetSymbolAddress((void**)&syn, g_syn);
    cudaGetSymbolAddress((void**)&mem, g_mem);
    cudaGetSymbolAddress((void**)&spk, g_spk);
    cudaGetSymbolAddress((void**)&R, g_R);
    cudaGetSymbolAddress((void**)&l, g_l);
    cudaGetSymbolAddress((void**)&ga, g_ga);
    cudaGetSymbolAddress((void**)&gl, g_gl);
    cudaGetSymbolAddress((void**)&fu, g_fu);
    cudaGetSymbolAddress((void**)&o, g_o);
    cudaGetSymbolAddress((void**)&part, g_part);
    cudaGetSymbolAddress((void**)&stats, g_stats);
    cudaGetSymbolAddress((void**)&apT, g_apT);
    cudaGetSymbolAddress((void**)&watT, g_watT);
    cudaGetSymbolAddress((void**)&wlsT, g_wlsT);
    cudaGetSymbolAddress((void**)&recT, g_recT);

    const dim3 gC(C_ / BN, TBN_ / BM);     // (3, 196)
    const dim3 gH(HID_ / BN, TBN_ / BM);   // (12, 196) fc1
    const dim3 gR(HID_ / BN, BN_ / BM);    // (12, 49)  rec dense
    const int nb75k = (NC_ + 255) / 256;
    const int nbBNC = (BNC_ + 255) / 256;
    const int nbMH  = (MH_ + 255) / 256;
    const dim3 tb32(32, 8);
    const dim3 gT384(C_ / 32, C_ / 32);    // (12, 12)
    const dim3 gT1536(HID_ / 32, HID_ / 32);

    // ---- weight transposes for gather-SpMM ----
    transpose_k<<<gT384, tb32>>>(ap_w, apT, C_, C_);
    transpose_k<<<gT384, tb32>>>(watt_w, watT, C_, C_);
    transpose_k<<<gT384, tb32>>>(wlsm_w, wlsT, C_, C_);
    transpose_k<<<gT1536, tb32>>>(rec_w, recT, HID_, HID_);

    // --- SSA branch ---
    sgemm_nt<<<gC, 256>>>(x, q_w, q_b, bq, TBN_, C_, C_);
    sgemm_nt<<<gC, 256>>>(x, k_w, k_b, bk, TBN_, C_, C_);
    sgemm_nt<<<gC, 256>>>(x, v_w, v_b, bv, TBN_, C_, C_);
    lif_seq3<<<dim3(nb75k, 3), 256>>>(bq, bk, bv, lif_w);

    attn_kernel<<<TB_ * H_, 256>>>(bq, bk, bv, ab);
    lif_seq<<<nbBNC, 256>>>(ab, T_, BNC_, BNC_, lif_w, 3);

    spmm_gather<2><<<TBN_, 256>>>(ab, apT, ap_b, af, C_, C_);   // ap: spike input
    lif_seq<<<nb75k, 256>>>(af, TB_, NC_, NC_, lif_w, 4);

    // --- LSM branch ---
    sgemm_nt<<<gH, 256>>>(x, fc1_w, fc1_b, curr, TBN_, HID_, C_);
    lsm_step0<<<nbMH, 256>>>(curr, rec_b, syn, mem, spk);
    // t=1: first-step spikes are very sparse -> gather
    spmm_gather<6><<<BN_, 256>>>(spk, recT, rec_b, R, HID_, HID_);
    lsm_step<<<nbMH, 256>>>(curr + (size_t)MH_, R, syn, mem, spk, spk + (size_t)MH_);
    // t=2,3: denser -> dense GEMM
    for (int t = 2; t < T_; t++) {
        sgemm_nt<<<gR, 256>>>(spk + (size_t)(t - 1) * MH_, rec_w, rec_b, R, BN_, HID_, HID_);
        lsm_step<<<nbMH, 256>>>(curr + (size_t)t * MH_, R, syn, mem,
                                spk + (size_t)(t - 1) * MH_, spk + (size_t)t * MH_);
    }
    sgemm_nt<<<gC, 256>>>(spk, fc2_w, fc2_b, l, TBN_, C_, HID_);
    bn_partial<<<98, 384>>>(l, part);
    bn_finalize<<<1, 384>>>(part, stats);
    bn_lif4<<<nbBNC, 256>>>(l, l, stats, bnl_g, bnl_b, lif_w, 5, nullptr);

    // --- ARIG fusion ---
    spmm_gather<2><<<TBN_, 256>>>(af, watT, watt_b, ga, C_, C_);  // watt: spike input
    spmm_gather<2><<<TBN_, 256>>>(l, wlsT, wlsm_b, gl, C_, C_);   // wlsm: spike input
    fuse_kernel<<<nbMH, 256>>>(af, l, ga, gl, fu);
    sgemm_nt<<<gC, 256>>>(fu, fp_w, fp_b, o, TBN_, C_, C_);
    bn_partial<<<98, 384>>>(o, part);
    bn_finalize<<<1, 384>>>(part, stats);
    bn_lif4<<<nbBNC, 256>>>(o, out, stats, bnf_g, bnf_b, lif_w, 6, x);
}

// round 11
// speedup vs baseline: 1.7027x; 1.0691x over previous
#include <cuda_runtime.h>
#include <math.h>
#include <stdint.h>

// ---------------- problem constants ----------------
#define T_    4
#define B_    32
#define N_    196
#define C_    384
#define H_    8
#define D_    48
#define HID_  1536
#define TB_   128           // T*B
#define NC_   75264         // N*C
#define BNC_  2408448       // B*N*C
#define TBN_  25088         // T*B*N
#define BN_   6272          // B*N
#define MH_   9633792       // BN_*HID_ == TBN_*C_
#define CC_   (C_ * C_)
#define HH_   (HID_ * HID_)

// ---------------- scratch (device globals; no runtime alloc allowed) ----------------
__device__ float g_bq[MH_];
__device__ float g_bk[MH_];
__device__ float g_bv[MH_];
__device__ float g_ab[MH_];
__device__ float g_af[MH_];
__device__ float g_curr[4 * MH_];
__device__ float g_syn[MH_];
__device__ float g_mem[MH_];
__device__ float g_spk[4 * MH_];
__device__ float g_R[MH_];
__device__ float g_l[MH_];
__device__ float g_ga[MH_];
__device__ float g_gl[MH_];
__device__ float g_fu[MH_];
__device__ float g_o[MH_];
__device__ float g_part[98 * 768];
__device__ float g_stats[768];   // [0:384) mu, [384:768) rstd
// transposed weights for gather-SpMM
__device__ float g_apT[CC_];
__device__ float g_watT[CC_];
__device__ float g_wlsT[CC_];
__device__ float g_fpT[CC_];
__device__ float g_recT[HH_];

// ---------------- f32x2 packed-FMA helpers ----------------
#define FMA2(D, A, B) \
    asm("fma.rn.f32x2 %0, %1, %2, %0;" : "+l"(D) : "l"(A), "l"(B))
#define PACK2(P, X, Y) \
    asm("mov.b64 %0, {%1, %2};" : "=l"(P) : "f"(X), "f"(Y))
#define UNPACK2(X, Y, P) \
    asm("mov.b64 {%0, %1}, %2;" : "=f"(X), "=f"(Y) : "l"(P))

// ================= SGEMM2 (BK=16: half the syncs; identical k-order) =================
#define BM 128
#define BN 128
#define BK 16

__global__ __launch_bounds__(256, 2)
void sgemm_nt(const float* __restrict__ A, const float* __restrict__ W,
              const float* __restrict__ bias, float* __restrict__ C,
              int M, int N, int K) {
    __shared__ float As[2][BK][BM];
    __shared__ float Bs[2][BK][BN];

    const int tid = threadIdx.x;
    const int bm = blockIdx.y * BM;
    const int bn = blockIdx.x * BN;

    // global load mapping: each thread loads 2 float4 of A and 2 of W per k-tile
    const int lrow = tid >> 2;          // 0..63
    const int lq = (tid & 3) * 4;       // k offset 0,4,8,12
    const float* Ap0 = A + (size_t)(bm + lrow) * K + lq;
    const float* Ap1 = A + (size_t)(bm + lrow + 64) * K + lq;
    const float* Wp0 = W + (size_t)(bn + lrow) * K + lq;
    const float* Wp1 = W + (size_t)(bn + lrow + 64) * K + lq;

    const int tx = tid & 15;
    const int ty = tid >> 4;

    unsigned long long accp[8][4];
#pragma unroll
    for (int i = 0; i < 8; i++)
#pragma unroll
        for (int jp = 0; jp < 4; jp++) accp[i][jp] = 0ull;

    // prologue: k-tile 0 -> buffer 0
    float4 a0 = *(const float4*)Ap0;
    float4 a1 = *(const float4*)Ap1;
    float4 w0 = *(const float4*)Wp0;
    float4 w1 = *(const float4*)Wp1;
    As[0][lq + 0][lrow] = a0.x; As[0][lq + 1][lrow] = a0.y;
    As[0][lq + 2][lrow] = a0.z; As[0][lq + 3][lrow] = a0.w;
    As[0][lq + 0][lrow + 64] = a1.x; As[0][lq + 1][lrow + 64] = a1.y;
    As[0][lq + 2][lrow + 64] = a1.z; As[0][lq + 3][lrow + 64] = a1.w;
    Bs[0][lq + 0][lrow] = w0.x; Bs[0][lq + 1][lrow] = w0.y;
    Bs[0][lq + 2][lrow] = w0.z; Bs[0][lq + 3][lrow] = w0.w;
    Bs[0][lq + 0][lrow + 64] = w1.x; Bs[0][lq + 1][lrow + 64] = w1.y;
    Bs[0][lq + 2][lrow + 64] = w1.z; Bs[0][lq + 3][lrow + 64] = w1.w;
    __syncthreads();

    const int nk = K / BK;
    for (int kt = 0; kt < nk; kt++) {
        const int cur = kt & 1;
        if (kt + 1 < nk) {
            const size_t off = (size_t)(kt + 1) * BK;
            a0 = *(const float4*)(Ap0 + off);
            a1 = *(const float4*)(Ap1 + off);
            w0 = *(const float4*)(Wp0 + off);
            w1 = *(const float4*)(Wp1 + off);
        }
#pragma unroll
        for (int kk = 0; kk < BK; kk++) {
            float4 av0 = *(const float4*)&As[cur][kk][ty * 4];
            float4 av1 = *(const float4*)&As[cur][kk][ty * 4 + 64];
            float4 bv0 = *(const float4*)&Bs[cur][kk][tx * 4];
            float4 bv1 = *(const float4*)&Bs[cur][kk][tx * 4 + 64];
            unsigned long long bp[4];
            PACK2(bp[0], bv0.x, bv0.y);
            PACK2(bp[1], bv0.z, bv0.w);
            PACK2(bp[2], bv1.x, bv1.y);
            PACK2(bp[3], bv1.z, bv1.w);
            float avs[8] = {av0.x, av0.y, av0.z, av0.w, av1.x, av1.y, av1.z, av1.w};
#pragma unroll
            for (int i = 0; i < 8; i++) {
                unsigned long long ap;
                PACK2(ap, avs[i], avs[i]);
                FMA2(accp[i][0], ap, bp[0]);
                FMA2(accp[i][1], ap, bp[1]);
                FMA2(accp[i][2], ap, bp[2]);
                FMA2(accp[i][3], ap, bp[3]);
            }
        }
        if (kt + 1 < nk) {
            const int nxt = cur ^ 1;
            As[nxt][lq + 0][lrow] = a0.x; As[nxt][lq + 1][lrow] = a0.y;
            As[nxt][lq + 2][lrow] = a0.z; As[nxt][lq + 3][lrow] = a0.w;
            As[nxt][lq + 0][lrow + 64] = a1.x; As[nxt][lq + 1][lrow + 64] = a1.y;
            As[nxt][lq + 2][lrow + 64] = a1.z; As[nxt][lq + 3][lrow + 64] = a1.w;
            Bs[nxt][lq + 0][lrow] = w0.x; Bs[nxt][lq + 1][lrow] = w0.y;
            Bs[nxt][lq + 2][lrow] = w0.z; Bs[nxt][lq + 3][lrow] = w0.w;
            Bs[nxt][lq + 0][lrow + 64] = w1.x; Bs[nxt][lq + 1][lrow + 64] = w1.y;
            Bs[nxt][lq + 2][lrow + 64] = w1.z; Bs[nxt][lq + 3][lrow + 64] = w1.w;
            __syncthreads();
        }
    }

    // epilogue: unpack, add bias, vectorized stores
#pragma unroll
    for (int i = 0; i < 8; i++) {
        const int row = bm + ty * 4 + (i & 3) + ((i >> 2) << 6);
#pragma unroll
        for (int jb = 0; jb < 2; jb++) {
            const int col = bn + tx * 4 + jb * 64;
            float4 bv4 = *(const float4*)&bias[col];
            float c0, c1, c2, c3;
            UNPACK2(c0, c1, accp[i][jb * 2 + 0]);
            UNPACK2(c2, c3, accp[i][jb * 2 + 1]);
            float4 v;
            v.x = c0 + bv4.x;
            v.y = c1 + bv4.y;
            v.z = c2 + bv4.z;
            v.w = c3 + bv4.w;
            *(float4*)&C[(size_t)row * N + col] = v;
        }
    }
}

// ================= gather-SpMM (binary): C[m,:] = bias + sum_{k: A[m,k]!=0} WT[k,:] ===========
template<int NV>
__global__ __launch_bounds__(256)
void spmm_gather(const float* __restrict__ A, const float* __restrict__ WT,
                 const float* __restrict__ bias, float* __restrict__ C,
                 int N, int K) {
    __shared__ short idxs[1536];
    __shared__ int wcnt[8];
    __shared__ int woff[8];
    __shared__ int s_nact;

    const int m = blockIdx.x;
    const int tid = threadIdx.x;
    const int lane = tid & 31;
    const int wid = tid >> 5;
    const float* arow = A + (size_t)m * K;
    const int nch = K >> 5;

    int cnt = 0;
    for (int c = wid; c < nch; c += 8) {
        unsigned mask = __ballot_sync(0xffffffffu, arow[c * 32 + lane] != 0.0f);
        cnt += __popc(mask);
    }
    if (lane == 0) wcnt[wid] = cnt;
    __syncthreads();
    if (tid == 0) {
        int tot = 0;
#pragma unroll
        for (int w = 0; w < 8; w++) { woff[w] = tot; tot += wcnt[w]; }
        s_nact = tot;
    }
    __syncthreads();

    int base = woff[wid];
    for (int c = wid; c < nch; c += 8) {
        int k = c * 32 + lane;
        bool act = (arow[k] != 0.0f);
        unsigned mask = __ballot_sync(0xffffffffu, act);
        if (act) idxs[base + __popc(mask & ((1u << lane) - 1u))] = (short)k;
        base += __popc(mask);
    }
    __syncthreads();

    const int nact = s_nact;
    float acc[NV];
#pragma unroll
    for (int v = 0; v < NV; v++) {
        int n = tid + v * 256;
        acc[v] = (n < N) ? bias[n] : 0.0f;
    }

    int i = 0;
    for (; i + 2 <= nact; i += 2) {
        const float* w0 = WT + (size_t)idxs[i] * N;
        const float* w1 = WT + (size_t)idxs[i + 1] * N;
        float r0[NV], r1[NV];
#pragma unroll
        for (int v = 0; v < NV; v++) {
            int n = tid + v * 256;
            if (n < N) { r0[v] = w0[n]; r1[v] = w1[n]; }
        }
#pragma unroll
        for (int v = 0; v < NV; v++) {
            int n = tid + v * 256;
            if (n < N) { acc[v] += r0[v]; acc[v] += r1[v]; }
        }
    }
    if (i < nact) {
        const float* w0 = WT + (size_t)idxs[i] * N;
#pragma unroll
        for (int v = 0; v < NV; v++) {
            int n = tid + v * 256;
            if (n < N) acc[v] += w0[n];
        }
    }

#pragma unroll
    for (int v = 0; v < NV; v++) {
        int n = tid + v * 256;
        if (n < N) C[(size_t)m * N + n] = acc[v];
    }
}

// ================= gather-SpMM (valued): C[m,:] = bias + sum_{k: A[m,k]!=0} A[m,k]*WT[k,:] ====
template<int NV>
__global__ __launch_bounds__(256)
void spmm_gather_val(const float* __restrict__ A, const float* __restrict__ WT,
                     const float* __restrict__ bias, float* __restrict__ C,
                     int N, int K) {
    __shared__ short idxs[1536];
    __shared__ float vals[1536];
    __shared__ int wcnt[8];
    __shared__ int woff[8];
    __shared__ int s_nact;

    const int m = blockIdx.x;
    const int tid = threadIdx.x;
    const int lane = tid & 31;
    const int wid = tid >> 5;
    const float* arow = A + (size_t)m * K;
    const int nch = K >> 5;

    int cnt = 0;
    for (int c = wid; c < nch; c += 8) {
        unsigned mask = __ballot_sync(0xffffffffu, arow[c * 32 + lane] != 0.0f);
        cnt += __popc(mask);
    }
    if (lane == 0) wcnt[wid] = cnt;
    __syncthreads();
    if (tid == 0) {
        int tot = 0;
#pragma unroll
        for (int w = 0; w < 8; w++) { woff[w] = tot; tot += wcnt[w]; }
        s_nact = tot;
    }
    __syncthreads();

    int base = woff[wid];
    for (int c = wid; c < nch; c += 8) {
        int k = c * 32 + lane;
        float a = arow[k];
        bool act = (a != 0.0f);
        unsigned mask = __ballot_sync(0xffffffffu, act);
        if (act) {
            int p = base + __popc(mask & ((1u << lane) - 1u));
            idxs[p] = (short)k;
            vals[p] = a;
        }
        base += __popc(mask);
    }
    __syncthreads();

    const int nact = s_nact;
    float acc[NV];
#pragma unroll
    for (int v = 0; v < NV; v++) {
        int n = tid + v * 256;
        acc[v] = (n < N) ? bias[n] : 0.0f;
    }

    for (int i = 0; i < nact; i++) {
        const float* w0 = WT + (size_t)idxs[i] * N;
        const float a = vals[i];
#pragma unroll
        for (int v = 0; v < NV; v++) {
            int n = tid + v * 256;
            if (n < N) acc[v] = fmaf(a, w0[n], acc[v]);
        }
    }

#pragma unroll
    for (int v = 0; v < NV; v++) {
        int n = tid + v * 256;
        if (n < N) C[(size_t)m * N + n] = acc[v];
    }
}

// ---------------- transpose W[Nw,Kw] -> WT[Kw,Nw] ----------------
__global__ void transpose_k(const float* __restrict__ W, float* __restrict__ WT,
                            int Nw, int Kw) {
    __shared__ float t[32][33];
    int bx = blockIdx.x * 32, by = blockIdx.y * 32;
    int x = bx + threadIdx.x;
#pragma unroll
    for (int j = 0; j < 32; j += 8) {
        int y = by + threadIdx.y + j;
        if (y < Nw && x < Kw) t[threadIdx.y + j][threadIdx.x] = W[(size_t)y * Kw + x];
    }
    __syncthreads();
    int x2 = by + threadIdx.x;
#pragma unroll
    for (int j = 0; j < 32; j += 8) {
        int y2 = bx + threadIdx.y + j;
        if (y2 < Kw && x2 < Nw) WT[(size_t)y2 * Nw + x2] = t[threadIdx.x][threadIdx.y + j];
    }
}

// ---------------- LIF scan (in-place), depth-4 prefetch ----------------
__global__ void lif_seq(float* __restrict__ buf, int steps, long stride, long nelem,
                        const float* __restrict__ lif_w, int widx) {
    long idx = (long)blockIdx.x * blockDim.x + threadIdx.x;
    if (idx >= nelem) return;
    const float decay = 1.0f / (1.0f + expf(-lif_w[widx]));
    float v = 0.0f;
    float xs[4];
#pragma unroll
    for (int t = 0; t < 4; t++)
        if (t < steps) xs[t] = buf[(long)t * stride + idx];
    for (int t = 0; t < steps; t++) {
        float x = xs[t & 3];
        if (t + 4 < steps) xs[t & 3] = buf[(long)(t + 4) * stride + idx];
        v = v + (x - v) * decay;
        float s = (v >= 1.0f) ? 1.0f : 0.0f;
        buf[(long)t * stride + idx] = s;
        v *= (1.0f - s);
    }
}

// ---------------- merged q/k/v LIF ----------------
__global__ void lif_seq3(float* __restrict__ b0, float* __restrict__ b1,
                         float* __restrict__ b2, const float* __restrict__ lif_w) {
    long idx = (long)blockIdx.x * blockDim.x + threadIdx.x;
    if (idx >= (long)NC_) return;
    const int which = blockIdx.y;
    float* buf = (which == 0) ? b0 : ((which == 1) ? b1 : b2);
    const float decay = 1.0f / (1.0f + expf(-lif_w[which]));
    float v = 0.0f;
    float xs[4];
#pragma unroll
    for (int t = 0; t < 4; t++) xs[t] = buf[(long)t * NC_ + idx];
    for (int t = 0; t < TB_; t++) {
        float x = xs[t & 3];
        if (t + 4 < TB_) xs[t & 3] = buf[(long)(t + 4) * NC_ + idx];
        v = v + (x - v) * decay;
        float s = (v >= 1.0f) ? 1.0f : 0.0f;
        buf[(long)t * NC_ + idx] = s;
        v *= (1.0f - s);
    }
}

// ---------------- spiking attention, one block per (t*B+b, h) ----------------
__global__ __launch_bounds__(256)
void attn_kernel(const float* __restrict__ sq, const float* __restrict__ sk,
                 const float* __restrict__ sv, float* __restrict__ abuf) {
    const int tb = blockIdx.x >> 3;
    const int h = blockIdx.x & 7;
    __shared__ unsigned long long qb[N_], kb[N_], vb[N_];
    __shared__ unsigned char cnt[N_ * 200];
    const int tid = threadIdx.x;

    for (int i = tid; i < N_; i += 256) { qb[i] = 0ull; kb[i] = 0ull; vb[i] = 0ull; }
    __syncthreads();

    const long base = (long)tb * NC_ + h * D_;
    for (int e = tid; e < N_ * D_; e += 256) {
        int n = e / D_, d = e % D_;
        long off = base + (long)n * C_ + d;
        unsigned long long bit = 1ull << d;
        if (sq[off] != 0.0f) atomicOr(&qb[n], bit);
        if (sk[off] != 0.0f) atomicOr(&kb[n], bit);
        if (sv[off] != 0.0f) atomicOr(&vb[n], bit);
    }
    __syncthreads();

    for (int i = tid; i < N_ * N_; i += 256) {
        int n = i / N_, m = i - n * N_;
        cnt[n * 200 + m] = (unsigned char)__popcll(qb[n] & kb[m]);
    }
    __syncthreads();

    const float scale = 0.14433756729740643f;  // 48^-0.5
    for (int o = tid; o < N_ * D_; o += 256) {
        int n = o / D_, d = o - n * D_;
        const unsigned char* crow = &cnt[n * 200];
        int acc = 0;
#pragma unroll 4
        for (int m = 0; m < N_; m++)
            acc += (int)crow[m] * (int)((vb[m] >> d) & 1ull);
        abuf[(long)tb * NC_ + h * (D_ * N_) + d * N_ + n] = scale * (float)acc;
    }
}

// ---------------- LSM (RSynaptic) elementwise steps ----------------
__global__ void lsm_step0(const float* __restrict__ curr, const float* __restrict__ rec_b,
                          float* __restrict__ syn, float* __restrict__ mem,
                          float* __restrict__ spk) {
    long idx = (long)blockIdx.x * blockDim.x + threadIdx.x;
    if (idx >= (long)MH_) return;
    int hc = (int)(idx % HID_);
    float s = curr[idx] + rec_b[hc];
    syn[idx] = s;
    mem[idx] = s;
    spk[idx] = (s - 1.0f >= 0.0f) ? 1.0f : 0.0f;
}

__global__ void lsm_step(const float* __restrict__ curr_t, const float* __restrict__ R,
                         float* __restrict__ syn, float* __restrict__ mem,
                         const float* __restrict__ spk_prev, float* __restrict__ spk_out) {
    long idx = (long)blockIdx.x * blockDim.x + threadIdx.x;
    if (idx >= (long)MH_) return;
    float sp = spk_prev[idx];
    float s = 0.9f * syn[idx] + curr_t[idx] + R[idx];
    float m = 0.8f * mem[idx] + s - sp * 1.0f;
    syn[idx] = s;
    mem[idx] = m;
    spk_out[idx] = (m - 1.0f >= 0.0f) ? 1.0f : 0.0f;
}

// ---------------- BatchNorm stats (deterministic 2-stage) ----------------
__global__ void bn_partial(const float* __restrict__ X, float* __restrict__ part) {
    int c = threadIdx.x;
    long r0 = (long)blockIdx.x * 256;
    float s = 0.0f, s2 = 0.0f;
    for (int r = 0; r < 256; r++) {
        float v = X[(r0 + r) * C_ + c];
        s += v;
        s2 += v * v;
    }
    part[blockIdx.x * 768 + c] = s;
    part[blockIdx.x * 768 + 384 + c] = s2;
}

__global__ void bn_finalize(const float* __restrict__ part, float* __restrict__ stats) {
    int c = threadIdx.x;
    float s = 0.0f, s2 = 0.0f;
    for (int p = 0; p < 98; p++) {
        s += part[p * 768 + c];
        s2 += part[p * 768 + 384 + c];
    }
    const float inv = 1.0f / 25088.0f;
    float m = s * inv;
    float var = s2 * inv - m * m;
    stats[c] = m;
    stats[384 + c] = 1.0f / sqrtf(var + 1e-5f);
}

// ---------------- fused BN-apply + 4-step LIF (+ optional residual) ----------------
__global__ void bn_lif4(const float* __restrict__ lin, float* __restrict__ out,
                        const float* __restrict__ stats,
                        const float* __restrict__ gamma, const float* __restrict__ beta,
                        const float* __restrict__ lif_w, int widx,
                        const float* __restrict__ xadd) {
    long idx = (long)blockIdx.x * blockDim.x + threadIdx.x;
    if (idx >= (long)BNC_) return;
    int c = (int)(idx % C_);
    float mu = stats[c], rstd = stats[384 + c];
    float gg = gamma[c], bb = beta[c];
    float decay = 1.0f / (1.0f + expf(-lif_w[widx]));
    float v = 0.0f;
    float xs[4];
#pragma unroll
    for (int t = 0; t < 4; t++) xs[t] = lin[(long)t * BNC_ + idx];
#pragma unroll
    for (int t = 0; t < 4; t++) {
        long o = (long)t * BNC_ + idx;
        float xv = (xs[t] - mu) * rstd * gg + bb;
        v = v + (xv - v) * decay;
        float s = (v >= 1.0f) ? 1.0f : 0.0f;
        v *= (1.0f - s);
        if (xadd) out[o] = xadd[o] + s;
        else      out[o] = s;
    }
}

// ---------------- ARIG fusion elementwise ----------------
__global__ void fuse_kernel(const float* __restrict__ af, const float* __restrict__ lf,
                            const float* __restrict__ ga, const float* __restrict__ gl,
                            float* __restrict__ fu) {
    long idx = (long)blockIdx.x * blockDim.x + threadIdx.x;
    if (idx >= (long)MH_) return;
    float gate_attn = 1.0f / (1.0f + expf(-gl[idx]));
    float gate_lsm  = 1.0f / (1.0f + expf(-ga[idx]));
    fu[idx] = af[idx] * gate_attn + lf[idx] * gate_lsm;
}

// ---------------- launch ----------------
extern "C" void kernel_launch(void* const* d_in, const int* in_sizes, int n_in,
                              void* d_out, int out_size) {
    const float* x      = (const float*)d_in[0];
    const float* q_w    = (const float*)d_in[1];
    const float* q_b    = (const float*)d_in[2];
    const float* k_w    = (const float*)d_in[3];
    const float* k_b    = (const float*)d_in[4];
    const float* v_w    = (const float*)d_in[5];
    const float* v_b    = (const float*)d_in[6];
    const float* ap_w   = (const float*)d_in[7];
    const float* ap_b   = (const float*)d_in[8];
    const float* fc1_w  = (const float*)d_in[9];
    const float* fc1_b  = (const float*)d_in[10];
    const float* rec_w  = (const float*)d_in[11];
    const float* rec_b  = (const float*)d_in[12];
    const float* fc2_w  = (const float*)d_in[13];
    const float* fc2_b  = (const float*)d_in[14];
    const float* bnl_g  = (const float*)d_in[15];
    const float* bnl_b  = (const float*)d_in[16];
    const float* watt_w = (const float*)d_in[17];
    const float* watt_b = (const float*)d_in[18];
    const float* wlsm_w = (const float*)d_in[19];
    const float* wlsm_b = (const float*)d_in[20];
    const float* fp_w   = (const float*)d_in[21];
    const float* fp_b   = (const float*)d_in[22];
    const float* bnf_g  = (const float*)d_in[23];
    const float* bnf_b  = (const float*)d_in[24];
    const float* lif_w  = (const float*)d_in[25];
    float* out = (float*)d_out;

    float *bq, *bk, *bv, *ab, *af, *curr, *syn, *mem, *spk, *R, *l, *ga, *gl, *fu, *o, *part, *stats;
    float *apT, *watT, *wlsT, *fpT, *recT;
    cudaGetSymbolAddress((void**)&bq, g_bq);
    cudaGetSymbolAddress((void**)&bk, g_bk);
    cudaGetSymbolAddress((void**)&bv, g_bv);
    cudaGetSymbolAddress((void**)&ab, g_ab);
    cudaGetSymbolAddress((void**)&af, g_af);
    cudaGetSymbolAddress((void**)&curr, g_curr);
    cudaGetSymbolAddress((void**)&syn, g_syn);
    cudaGetSymbolAddress((void**)&mem, g_mem);
    cudaGetSymbolAddress((void**)&spk, g_spk);
    cudaGetSymbolAddress((void**)&R, g_R);
    cudaGetSymbolAddress((void**)&l, g_l);
    cudaGetSymbolAddress((void**)&ga, g_ga);
    cudaGetSymbolAddress((void**)&gl, g_gl);
    cudaGetSymbolAddress((void**)&fu, g_fu);
    cudaGetSymbolAddress((void**)&o, g_o);
    cudaGetSymbolAddress((void**)&part, g_part);
    cudaGetSymbolAddress((void**)&stats, g_stats);
    cudaGetSymbolAddress((void**)&apT, g_apT);
    cudaGetSymbolAddress((void**)&watT, g_watT);
    cudaGetSymbolAddress((void**)&wlsT, g_wlsT);
    cudaGetSymbolAddress((void**)&fpT, g_fpT);
    cudaGetSymbolAddress((void**)&recT, g_recT);

    const dim3 gC(C_ / BN, TBN_ / BM);     // (3, 196)
    const dim3 gH(HID_ / BN, TBN_ / BM);   // (12, 196) fc1
    const dim3 gR(HID_ / BN, BN_ / BM);    // (12, 49)  rec dense
    const int nb75k = (NC_ + 255) / 256;
    const int nbBNC = (BNC_ + 255) / 256;
    const int nbMH  = (MH_ + 255) / 256;
    const dim3 tb32(32, 8);
    const dim3 gT384(C_ / 32, C_ / 32);
    const dim3 gT1536(HID_ / 32, HID_ / 32);

    // ---- weight transposes for gather-SpMM ----
    transpose_k<<<gT384, tb32>>>(ap_w, apT, C_, C_);
    transpose_k<<<gT384, tb32>>>(watt_w, watT, C_, C_);
    transpose_k<<<gT384, tb32>>>(wlsm_w, wlsT, C_, C_);
    transpose_k<<<gT384, tb32>>>(fp_w, fpT, C_, C_);
    transpose_k<<<gT1536, tb32>>>(rec_w, recT, HID_, HID_);

    // --- SSA branch ---
    sgemm_nt<<<gC, 256>>>(x, q_w, q_b, bq, TBN_, C_, C_);
    sgemm_nt<<<gC, 256>>>(x, k_w, k_b, bk, TBN_, C_, C_);
    sgemm_nt<<<gC, 256>>>(x, v_w, v_b, bv, TBN_, C_, C_);
    lif_seq3<<<dim3(nb75k, 3), 256>>>(bq, bk, bv, lif_w);

    attn_kernel<<<TB_ * H_, 256>>>(bq, bk, bv, ab);
    lif_seq<<<nbBNC, 256>>>(ab, T_, BNC_, BNC_, lif_w, 3);

    spmm_gather<2><<<TBN_, 256>>>(ab, apT, ap_b, af, C_, C_);
    lif_seq<<<nb75k, 256>>>(af, TB_, NC_, NC_, lif_w, 4);

    // --- LSM branch ---
    sgemm_nt<<<gH, 256>>>(x, fc1_w, fc1_b, curr, TBN_, HID_, C_);
    lsm_step0<<<nbMH, 256>>>(curr, rec_b, syn, mem, spk);
    // t=1, t=2: spikes sparse enough -> gather
    spmm_gather<6><<<BN_, 256>>>(spk, recT, rec_b, R, HID_, HID_);
    lsm_step<<<nbMH, 256>>>(curr + (size_t)MH_, R, syn, mem, spk, spk + (size_t)MH_);
    spmm_gather<6><<<BN_, 256>>>(spk + (size_t)MH_, recT, rec_b, R, HID_, HID_);
    lsm_step<<<nbMH, 256>>>(curr + 2 * (size_t)MH_, R, syn, mem,
                            spk + (size_t)MH_, spk + 2 * (size_t)MH_);
    // t=3: denser -> dense GEMM
    sgemm_nt<<<gR, 256>>>(spk + 2 * (size_t)MH_, rec_w, rec_b, R, BN_, HID_, HID_);
    lsm_step<<<nbMH, 256>>>(curr + 3 * (size_t)MH_, R, syn, mem,
                            spk + 2 * (size_t)MH_, spk + 3 * (size_t)MH_);
    sgemm_nt<<<gC, 256>>>(spk, fc2_w, fc2_b, l, TBN_, C_, HID_);
    bn_partial<<<98, 384>>>(l, part);
    bn_finalize<<<1, 384>>>(part, stats);
    bn_lif4<<<nbBNC, 256>>>(l, l, stats, bnl_g, bnl_b, lif_w, 5, nullptr);

    // --- ARIG fusion ---
    spmm_gather<2><<<TBN_, 256>>>(af, watT, watt_b, ga, C_, C_);
    spmm_gather<2><<<TBN_, 256>>>(l, wlsT, wlsm_b, gl, C_, C_);
    fuse_kernel<<<nbMH, 256>>>(af, l, ga, gl, fu);
    spmm_gather_val<2><<<TBN_, 256>>>(fu, fpT, fp_b, o, C_, C_);   // fu ~96% exact zeros
    bn_partial<<<98, 384>>>(o, part);
    bn_finalize<<<1, 384>>>(part, stats);
    bn_lif4<<<nbBNC, 256>>>(o, out, stats, bnf_g, bnf_b, lif_w, 6, x);
}

// round 12
// speedup vs baseline: 2.0934x; 1.2294x over previous
#include <cuda_runtime.h>
#include <math.h>
#include <stdint.h>

// ---------------- problem constants ----------------
#define T_    4
#define B_    32
#define N_    196
#define C_    384
#define H_    8
#define D_    48
#define HID_  1536
#define TB_   128           // T*B
#define NC_   75264         // N*C
#define BNC_  2408448       // B*N*C
#define TBN_  25088         // T*B*N
#define BN_   6272          // B*N
#define MH_   9633792       // BN_*HID_ == TBN_*C_
#define CC_   (C_ * C_)
#define HC_   (HID_ * C_)
#define HH_   (HID_ * HID_)

// ---------------- scratch (device globals; no runtime alloc allowed) ----------------
__device__ float g_bq[MH_];
__device__ float g_bk[MH_];
__device__ float g_bv[MH_];
__device__ float g_ab[MH_];
__device__ float g_af[MH_];
__device__ float g_curr[4 * MH_];
__device__ float g_syn[MH_];
__device__ float g_mem[MH_];
__device__ float g_spk[4 * MH_];
__device__ float g_R[MH_];
__device__ float g_l[MH_];
__device__ float g_ga[MH_];
__device__ float g_gl[MH_];
__device__ float g_fu[MH_];
__device__ float g_o[MH_];
__device__ float g_part[98 * 768];
__device__ float g_stats[768];   // [0:384) mu, [384:768) rstd
// transposed weights for gather-SpMM
__device__ float g_apT[CC_];
__device__ float g_watT[CC_];
__device__ float g_wlsT[CC_];
__device__ float g_fpT[CC_];
__device__ float g_recT[HH_];
__device__ float g_fc2T[HC_];

// ---------------- f32x2 packed-FMA helpers ----------------
#define FMA2(D, A, B) \
    asm("fma.rn.f32x2 %0, %1, %2, %0;" : "+l"(D) : "l"(A), "l"(B))
#define PACK2(P, X, Y) \
    asm("mov.b64 %0, {%1, %2};" : "=l"(P) : "f"(X), "f"(Y))
#define UNPACK2(X, Y, P) \
    asm("mov.b64 {%0, %1}, %2;" : "=f"(X), "=f"(Y) : "l"(P))

// ================= SGEMM2 (BK=16, round-11 proven, unchanged) =================
#define BM 128
#define BN 128
#define BK 16

__global__ __launch_bounds__(256, 2)
void sgemm_nt(const float* __restrict__ A, const float* __restrict__ W,
              const float* __restrict__ bias, float* __restrict__ C,
              int M, int N, int K) {
    __shared__ float As[2][BK][BM];
    __shared__ float Bs[2][BK][BN];

    const int tid = threadIdx.x;
    const int bm = blockIdx.y * BM;
    const int bn = blockIdx.x * BN;

    const int lrow = tid >> 2;
    const int lq = (tid & 3) * 4;
    const float* Ap0 = A + (size_t)(bm + lrow) * K + lq;
    const float* Ap1 = A + (size_t)(bm + lrow + 64) * K + lq;
    const float* Wp0 = W + (size_t)(bn + lrow) * K + lq;
    const float* Wp1 = W + (size_t)(bn + lrow + 64) * K + lq;

    const int tx = tid & 15;
    const int ty = tid >> 4;

    unsigned long long accp[8][4];
#pragma unroll
    for (int i = 0; i < 8; i++)
#pragma unroll
        for (int jp = 0; jp < 4; jp++) accp[i][jp] = 0ull;

    float4 a0 = *(const float4*)Ap0;
    float4 a1 = *(const float4*)Ap1;
    float4 w0 = *(const float4*)Wp0;
    float4 w1 = *(const float4*)Wp1;
    As[0][lq + 0][lrow] = a0.x; As[0][lq + 1][lrow] = a0.y;
    As[0][lq + 2][lrow] = a0.z; As[0][lq + 3][lrow] = a0.w;
    As[0][lq + 0][lrow + 64] = a1.x; As[0][lq + 1][lrow + 64] = a1.y;
    As[0][lq + 2][lrow + 64] = a1.z; As[0][lq + 3][lrow + 64] = a1.w;
    Bs[0][lq + 0][lrow] = w0.x; Bs[0][lq + 1][lrow] = w0.y;
    Bs[0][lq + 2][lrow] = w0.z; Bs[0][lq + 3][lrow] = w0.w;
    Bs[0][lq + 0][lrow + 64] = w1.x; Bs[0][lq + 1][lrow + 64] = w1.y;
    Bs[0][lq + 2][lrow + 64] = w1.z; Bs[0][lq + 3][lrow + 64] = w1.w;
    __syncthreads();

    const int nk = K / BK;
    for (int kt = 0; kt < nk; kt++) {
        const int cur = kt & 1;
        if (kt + 1 < nk) {
            const size_t off = (size_t)(kt + 1) * BK;
            a0 = *(const float4*)(Ap0 + off);
            a1 = *(const float4*)(Ap1 + off);
            w0 = *(const float4*)(Wp0 + off);
            w1 = *(const float4*)(Wp1 + off);
        }
#pragma unroll
        for (int kk = 0; kk < BK; kk++) {
            float4 av0 = *(const float4*)&As[cur][kk][ty * 4];
            float4 av1 = *(const float4*)&As[cur][kk][ty * 4 + 64];
            float4 bv0 = *(const float4*)&Bs[cur][kk][tx * 4];
            float4 bv1 = *(const float4*)&Bs[cur][kk][tx * 4 + 64];
            unsigned long long bp[4];
            PACK2(bp[0], bv0.x, bv0.y);
            PACK2(bp[1], bv0.z, bv0.w);
            PACK2(bp[2], bv1.x, bv1.y);
            PACK2(bp[3], bv1.z, bv1.w);
            float avs[8] = {av0.x, av0.y, av0.z, av0.w, av1.x, av1.y, av1.z, av1.w};
#pragma unroll
            for (int i = 0; i < 8; i++) {
                unsigned long long ap;
                PACK2(ap, avs[i], avs[i]);
                FMA2(accp[i][0], ap, bp[0]);
                FMA2(accp[i][1], ap, bp[1]);
                FMA2(accp[i][2], ap, bp[2]);
                FMA2(accp[i][3], ap, bp[3]);
            }
        }
        if (kt + 1 < nk) {
            const int nxt = cur ^ 1;
            As[nxt][lq + 0][lrow] = a0.x; As[nxt][lq + 1][lrow] = a0.y;
            As[nxt][lq + 2][lrow] = a0.z; As[nxt][lq + 3][lrow] = a0.w;
            As[nxt][lq + 0][lrow + 64] = a1.x; As[nxt][lq + 1][lrow + 64] = a1.y;
            As[nxt][lq + 2][lrow + 64] = a1.z; As[nxt][lq + 3][lrow + 64] = a1.w;
            Bs[nxt][lq + 0][lrow] = w0.x; Bs[nxt][lq + 1][lrow] = w0.y;
            Bs[nxt][lq + 2][lrow] = w0.z; Bs[nxt][lq + 3][lrow] = w0.w;
            Bs[nxt][lq + 0][lrow + 64] = w1.x; Bs[nxt][lq + 1][lrow + 64] = w1.y;
            Bs[nxt][lq + 2][lrow + 64] = w1.z; Bs[nxt][lq + 3][lrow + 64] = w1.w;
            __syncthreads();
        }
    }

#pragma unroll
    for (int i = 0; i < 8; i++) {
        const int row = bm + ty * 4 + (i & 3) + ((i >> 2) << 6);
#pragma unroll
        for (int jb = 0; jb < 2; jb++) {
            const int col = bn + tx * 4 + jb * 64;
            float4 bv4 = *(const float4*)&bias[col];
            float c0, c1, c2, c3;
            UNPACK2(c0, c1, accp[i][jb * 2 + 0]);
            UNPACK2(c2, c3, accp[i][jb * 2 + 1]);
            float4 v;
            v.x = c0 + bv4.x;
            v.y = c1 + bv4.y;
            v.z = c2 + bv4.z;
            v.w = c3 + bv4.w;
            *(float4*)&C[(size_t)row * N + col] = v;
        }
    }
}

// ================= gather-SpMM (binary) =================
template<int NV>
__global__ __launch_bounds__(256)
void spmm_gather(const float* __restrict__ A, const float* __restrict__ WT,
                 const float* __restrict__ bias, float* __restrict__ C,
                 int N, int K) {
    __shared__ short idxs[1536];
    __shared__ int wcnt[8];
    __shared__ int woff[8];
    __shared__ int s_nact;

    const int m = blockIdx.x;
    const int tid = threadIdx.x;
    const int lane = tid & 31;
    const int wid = tid >> 5;
    const float* arow = A + (size_t)m * K;
    const int nch = K >> 5;

    int cnt = 0;
    for (int c = wid; c < nch; c += 8) {
        unsigned mask = __ballot_sync(0xffffffffu, arow[c * 32 + lane] != 0.0f);
        cnt += __popc(mask);
    }
    if (lane == 0) wcnt[wid] = cnt;
    __syncthreads();
    if (tid == 0) {
        int tot = 0;
#pragma unroll
        for (int w = 0; w < 8; w++) { woff[w] = tot; tot += wcnt[w]; }
        s_nact = tot;
    }
    __syncthreads();

    int base = woff[wid];
    for (int c = wid; c < nch; c += 8) {
        int k = c * 32 + lane;
        bool act = (arow[k] != 0.0f);
        unsigned mask = __ballot_sync(0xffffffffu, act);
        if (act) idxs[base + __popc(mask & ((1u << lane) - 1u))] = (short)k;
        base += __popc(mask);
    }
    __syncthreads();

    const int nact = s_nact;
    float acc[NV];
#pragma unroll
    for (int v = 0; v < NV; v++) {
        int n = tid + v * 256;
        acc[v] = (n < N) ? bias[n] : 0.0f;
    }

    int i = 0;
    for (; i + 2 <= nact; i += 2) {
        const float* w0 = WT + (size_t)idxs[i] * N;
        const float* w1 = WT + (size_t)idxs[i + 1] * N;
        float r0[NV], r1[NV];
#pragma unroll
        for (int v = 0; v < NV; v++) {
            int n = tid + v * 256;
            if (n < N) { r0[v] = w0[n]; r1[v] = w1[n]; }
        }
#pragma unroll
        for (int v = 0; v < NV; v++) {
            int n = tid + v * 256;
            if (n < N) { acc[v] += r0[v]; acc[v] += r1[v]; }
        }
    }
    if (i < nact) {
        const float* w0 = WT + (size_t)idxs[i] * N;
#pragma unroll
        for (int v = 0; v < NV; v++) {
            int n = tid + v * 256;
            if (n < N) acc[v] += w0[n];
        }
    }

#pragma unroll
    for (int v = 0; v < NV; v++) {
        int n = tid + v * 256;
        if (n < N) C[(size_t)m * N + n] = acc[v];
    }
}

// ================= gather-SpMM (valued) =================
template<int NV>
__global__ __launch_bounds__(256)
void spmm_gather_val(const float* __restrict__ A, const float* __restrict__ WT,
                     const float* __restrict__ bias, float* __restrict__ C,
                     int N, int K) {
    __shared__ short idxs[1536];
    __shared__ float vals[1536];
    __shared__ int wcnt[8];
    __shared__ int woff[8];
    __shared__ int s_nact;

    const int m = blockIdx.x;
    const int tid = threadIdx.x;
    const int lane = tid & 31;
    const int wid = tid >> 5;
    const float* arow = A + (size_t)m * K;
    const int nch = K >> 5;

    int cnt = 0;
    for (int c = wid; c < nch; c += 8) {
        unsigned mask = __ballot_sync(0xffffffffu, arow[c * 32 + lane] != 0.0f);
        cnt += __popc(mask);
    }
    if (lane == 0) wcnt[wid] = cnt;
    __syncthreads();
    if (tid == 0) {
        int tot = 0;
#pragma unroll
        for (int w = 0; w < 8; w++) { woff[w] = tot; tot += wcnt[w]; }
        s_nact = tot;
    }
    __syncthreads();

    int base = woff[wid];
    for (int c = wid; c < nch; c += 8) {
        int k = c * 32 + lane;
        float a = arow[k];
        bool act = (a != 0.0f);
        unsigned mask = __ballot_sync(0xffffffffu, act);
        if (act) {
            int p = base + __popc(mask & ((1u << lane) - 1u));
            idxs[p] = (short)k;
            vals[p] = a;
        }
        base += __popc(mask);
    }
    __syncthreads();

    const int nact = s_nact;
    float acc[NV];
#pragma unroll
    for (int v = 0; v < NV; v++) {
        int n = tid + v * 256;
        acc[v] = (n < N) ? bias[n] : 0.0f;
    }

    for (int i = 0; i < nact; i++) {
        const float* w0 = WT + (size_t)idxs[i] * N;
        const float a = vals[i];
#pragma unroll
        for (int v = 0; v < NV; v++) {
            int n = tid + v * 256;
            if (n < N) acc[v] = fmaf(a, w0[n], acc[v]);
        }
    }

#pragma unroll
    for (int v = 0; v < NV; v++) {
        int n = tid + v * 256;
        if (n < N) C[(size_t)m * N + n] = acc[v];
    }
}

// ---------------- transpose W[Nw,Kw] -> WT[Kw,Nw] ----------------
__global__ void transpose_k(const float* __restrict__ W, float* __restrict__ WT,
                            int Nw, int Kw) {
    __shared__ float t[32][33];
    int bx = blockIdx.x * 32, by = blockIdx.y * 32;
    int x = bx + threadIdx.x;
#pragma unroll
    for (int j = 0; j < 32; j += 8) {
        int y = by + threadIdx.y + j;
        if (y < Nw && x < Kw) t[threadIdx.y + j][threadIdx.x] = W[(size_t)y * Kw + x];
    }
    __syncthreads();
    int x2 = by + threadIdx.x;
#pragma unroll
    for (int j = 0; j < 32; j += 8) {
        int y2 = bx + threadIdx.y + j;
        if (y2 < Kw && x2 < Nw) WT[(size_t)y2 * Nw + x2] = t[threadIdx.x][threadIdx.y + j];
    }
}

// ---------------- LIF scan (in-place), depth-4 prefetch ----------------
__global__ void lif_seq(float* __restrict__ buf, int steps, long stride, long nelem,
                        const float* __restrict__ lif_w, int widx) {
    long idx = (long)blockIdx.x * blockDim.x + threadIdx.x;
    if (idx >= nelem) return;
    const float decay = 1.0f / (1.0f + expf(-lif_w[widx]));
    float v = 0.0f;
    float xs[4];
#pragma unroll
    for (int t = 0; t < 4; t++)
        if (t < steps) xs[t] = buf[(long)t * stride + idx];
    for (int t = 0; t < steps; t++) {
        float x = xs[t & 3];
        if (t + 4 < steps) xs[t & 3] = buf[(long)(t + 4) * stride + idx];
        v = v + (x - v) * decay;
        float s = (v >= 1.0f) ? 1.0f : 0.0f;
        buf[(long)t * stride + idx] = s;
        v *= (1.0f - s);
    }
}

// ---------------- merged q/k/v LIF ----------------
__global__ void lif_seq3(float* __restrict__ b0, float* __restrict__ b1,
                         float* __restrict__ b2, const float* __restrict__ lif_w) {
    long idx = (long)blockIdx.x * blockDim.x + threadIdx.x;
    if (idx >= (long)NC_) return;
    const int which = blockIdx.y;
    float* buf = (which == 0) ? b0 : ((which == 1) ? b1 : b2);
    const float decay = 1.0f / (1.0f + expf(-lif_w[which]));
    float v = 0.0f;
    float xs[4];
#pragma unroll
    for (int t = 0; t < 4; t++) xs[t] = buf[(long)t * NC_ + idx];
    for (int t = 0; t < TB_; t++) {
        float x = xs[t & 3];
        if (t + 4 < TB_) xs[t & 3] = buf[(long)(t + 4) * NC_ + idx];
        v = v + (x - v) * decay;
        float s = (v >= 1.0f) ? 1.0f : 0.0f;
        buf[(long)t * NC_ + idx] = s;
        v *= (1.0f - s);
    }
}

// ---------------- spiking attention with v-sparsity fast path ----------------
// a[n,d] = scale * sum_m popc(q[n]&k[m]) * vbit[m,d]. Active (m,d) pairs are
// enumerated deterministically (serial m-order scan); if few, each output just
// sums over that list (integer-exact, same sum-then-scale as the dense path).
__global__ __launch_bounds__(256)
void attn_kernel(const float* __restrict__ sq, const float* __restrict__ sk,
                 const float* __restrict__ sv, float* __restrict__ abuf) {
    const int tb = blockIdx.x >> 3;
    const int h = blockIdx.x & 7;
    __shared__ unsigned long long qb[N_], kb[N_], vb[N_];
    __shared__ unsigned char cnt[N_ * 200];
    __shared__ int pairs[768];
    __shared__ int s_np;
    const int tid = threadIdx.x;

    for (int i = tid; i < N_; i += 256) { qb[i] = 0ull; kb[i] = 0ull; vb[i] = 0ull; }
    __syncthreads();

    const long base = (long)tb * NC_ + h * D_;
    for (int e = tid; e < N_ * D_; e += 256) {
        int n = e / D_, d = e % D_;
        long off = base + (long)n * C_ + d;
        unsigned long long bit = 1ull << d;
        if (sq[off] != 0.0f) atomicOr(&qb[n], bit);
        if (sk[off] != 0.0f) atomicOr(&kb[n], bit);
        if (sv[off] != 0.0f) atomicOr(&vb[n], bit);
    }
    __syncthreads();

    // deterministic active-pair enumeration (m-major, d ascending)
    if (tid == 0) {
        int np = 0;
        for (int m = 0; m < N_; m++) {
            unsigned long long w = vb[m];
            while (w) {
                int d = __ffsll((long long)w) - 1;
                if (np < 768) pairs[np] = (m << 6) | d;
                np++;
                w &= w - 1;
            }
        }
        s_np = np;
    }
    __syncthreads();

    const float scale = 0.14433756729740643f;  // 48^-0.5
    const int np = s_np;
    const long obase = (long)tb * NC_ + h * (D_ * N_);

    if (np <= 768) {
        // sparse path: per output, integer sum over the active pair list
        for (int o = tid; o < N_ * D_; o += 256) {
            int n = o / D_, d = o - n * D_;
            int acc = 0;
            for (int p = 0; p < np; p++) {
                int pm = pairs[p];
                if ((pm & 63) == d) acc += __popcll(qb[n] & kb[pm >> 6]);
            }
            abuf[obase + d * N_ + n] = scale * (float)acc;
        }
        return;
    }

    // dense fallback (original path)
    for (int i = tid; i < N_ * N_; i += 256) {
        int n = i / N_, m = i - n * N_;
        cnt[n * 200 + m] = (unsigned char)__popcll(qb[n] & kb[m]);
    }
    __syncthreads();

    for (int o = tid; o < N_ * D_; o += 256) {
        int n = o / D_, d = o - n * D_;
        const unsigned char* crow = &cnt[n * 200];
        int acc = 0;
#pragma unroll 4
        for (int m = 0; m < N_; m++)
            acc += (int)crow[m] * (int)((vb[m] >> d) & 1ull);
        abuf[obase + d * N_ + n] = scale * (float)acc;
    }
}

// ---------------- LSM (RSynaptic) elementwise steps ----------------
__global__ void lsm_step0(const float* __restrict__ curr, const float* __restrict__ rec_b,
                          float* __restrict__ syn, float* __restrict__ mem,
                          float* __restrict__ spk) {
    long idx = (long)blockIdx.x * blockDim.x + threadIdx.x;
    if (idx >= (long)MH_) return;
    int hc = (int)(idx % HID_);
    float s = curr[idx] + rec_b[hc];
    syn[idx] = s;
    mem[idx] = s;
    spk[idx] = (s - 1.0f >= 0.0f) ? 1.0f : 0.0f;
}

__global__ void lsm_step(const float* __restrict__ curr_t, const float* __restrict__ R,
                         float* __restrict__ syn, float* __restrict__ mem,
                         const float* __restrict__ spk_prev, float* __restrict__ spk_out) {
    long idx = (long)blockIdx.x * blockDim.x + threadIdx.x;
    if (idx >= (long)MH_) return;
    float sp = spk_prev[idx];
    float s = 0.9f * syn[idx] + curr_t[idx] + R[idx];
    float m = 0.8f * mem[idx] + s - sp * 1.0f;
    syn[idx] = s;
    mem[idx] = m;
    spk_out[idx] = (m - 1.0f >= 0.0f) ? 1.0f : 0.0f;
}

// ---------------- BatchNorm stats (deterministic 2-stage) ----------------
__global__ void bn_partial(const float* __restrict__ X, float* __restrict__ part) {
    int c = threadIdx.x;
    long r0 = (long)blockIdx.x * 256;
    float s = 0.0f, s2 = 0.0f;
    for (int r = 0; r < 256; r++) {
        float v = X[(r0 + r) * C_ + c];
        s += v;
        s2 += v * v;
    }
    part[blockIdx.x * 768 + c] = s;
    part[blockIdx.x * 768 + 384 + c] = s2;
}

__global__ void bn_finalize(const float* __restrict__ part, float* __restrict__ stats) {
    int c = threadIdx.x;
    float s = 0.0f, s2 = 0.0f;
    for (int p = 0; p < 98; p++) {
        s += part[p * 768 + c];
        s2 += part[p * 768 + 384 + c];
    }
    const float inv = 1.0f / 25088.0f;
    float m = s * inv;
    float var = s2 * inv - m * m;
    stats[c] = m;
    stats[384 + c] = 1.0f / sqrtf(var + 1e-5f);
}

// ---------------- fused BN-apply + 4-step LIF (+ optional residual) ----------------
__global__ void bn_lif4(const float* __restrict__ lin, float* __restrict__ out,
                        const float* __restrict__ stats,
                        const float* __restrict__ gamma, const float* __restrict__ beta,
                        const float* __restrict__ lif_w, int widx,
                        const float* __restrict__ xadd) {
    long idx = (long)blockIdx.x * blockDim.x + threadIdx.x;
    if (idx >= (long)BNC_) return;
    int c = (int)(idx % C_);
    float mu = stats[c], rstd = stats[384 + c];
    float gg = gamma[c], bb = beta[c];
    float decay = 1.0f / (1.0f + expf(-lif_w[widx]));
    float v = 0.0f;
    float xs[4];
#pragma unroll
    for (int t = 0; t < 4; t++) xs[t] = lin[(long)t * BNC_ + idx];
#pragma unroll
    for (int t = 0; t < 4; t++) {
        long o = (long)t * BNC_ + idx;
        float xv = (xs[t] - mu) * rstd * gg + bb;
        v = v + (xv - v) * decay;
        float s = (v >= 1.0f) ? 1.0f : 0.0f;
        v *= (1.0f - s);
        if (xadd) out[o] = xadd[o] + s;
        else      out[o] = s;
    }
}

// ---------------- ARIG fusion elementwise ----------------
__global__ void fuse_kernel(const float* __restrict__ af, const float* __restrict__ lf,
                            const float* __restrict__ ga, const float* __restrict__ gl,
                            float* __restrict__ fu) {
    long idx = (long)blockIdx.x * blockDim.x + threadIdx.x;
    if (idx >= (long)MH_) return;
    float gate_attn = 1.0f / (1.0f + expf(-gl[idx]));
    float gate_lsm  = 1.0f / (1.0f + expf(-ga[idx]));
    fu[idx] = af[idx] * gate_attn + lf[idx] * gate_lsm;
}

// ---------------- launch ----------------
extern "C" void kernel_launch(void* const* d_in, const int* in_sizes, int n_in,
                              void* d_out, int out_size) {
    const float* x      = (const float*)d_in[0];
    const float* q_w    = (const float*)d_in[1];
    const float* q_b    = (const float*)d_in[2];
    const float* k_w    = (const float*)d_in[3];
    const float* k_b    = (const float*)d_in[4];
    const float* v_w    = (const float*)d_in[5];
    const float* v_b    = (const float*)d_in[6];
    const float* ap_w   = (const float*)d_in[7];
    const float* ap_b   = (const float*)d_in[8];
    const float* fc1_w  = (const float*)d_in[9];
    const float* fc1_b  = (const float*)d_in[10];
    const float* rec_w  = (const float*)d_in[11];
    const float* rec_b  = (const float*)d_in[12];
    const float* fc2_w  = (const float*)d_in[13];
    const float* fc2_b  = (const float*)d_in[14];
    const float* bnl_g  = (const float*)d_in[15];
    const float* bnl_b  = (const float*)d_in[16];
    const float* watt_w = (const float*)d_in[17];
    const float* watt_b = (const float*)d_in[18];
    const float* wlsm_w = (const float*)d_in[19];
    const float* wlsm_b = (const float*)d_in[20];
    const float* fp_w   = (const float*)d_in[21];
    const float* fp_b   = (const float*)d_in[22];
    const float* bnf_g  = (const float*)d_in[23];
    const float* bnf_b  = (const float*)d_in[24];
    const float* lif_w  = (const float*)d_in[25];
    float* out = (float*)d_out;

    float *bq, *bk, *bv, *ab, *af, *curr, *syn, *mem, *spk, *R, *l, *ga, *gl, *fu, *o, *part, *stats;
    float *apT, *watT, *wlsT, *fpT, *recT, *fc2T;
    cudaGetSymbolAddress((void**)&bq, g_bq);
    cudaGetSymbolAddress((void**)&bk, g_bk);
    cudaGetSymbolAddress((void**)&bv, g_bv);
    cudaGetSymbolAddress((void**)&ab, g_ab);
    cudaGetSymbolAddress((void**)&af, g_af);
    cudaGetSymbolAddress((void**)&curr, g_curr);
    cudaGetSymbolAddress((void**)&syn, g_syn);
    cudaGetSymbolAddress((void**)&mem, g_mem);
    cudaGetSymbolAddress((void**)&spk, g_spk);
    cudaGetSymbolAddress((void**)&R, g_R);
    cudaGetSymbolAddress((void**)&l, g_l);
    cudaGetSymbolAddress((void**)&ga, g_ga);
    cudaGetSymbolAddress((void**)&gl, g_gl);
    cudaGetSymbolAddress((void**)&fu, g_fu);
    cudaGetSymbolAddress((void**)&o, g_o);
    cudaGetSymbolAddress((void**)&part, g_part);
    cudaGetSymbolAddress((void**)&stats, g_stats);
    cudaGetSymbolAddress((void**)&apT, g_apT);
    cudaGetSymbolAddress((void**)&watT, g_watT);
    cudaGetSymbolAddress((void**)&wlsT, g_wlsT);
    cudaGetSymbolAddress((void**)&fpT, g_fpT);
    cudaGetSymbolAddress((void**)&recT, g_recT);
    cudaGetSymbolAddress((void**)&fc2T, g_fc2T);

    const dim3 gC(C_ / BN, TBN_ / BM);     // (3, 196)
    const dim3 gH(HID_ / BN, TBN_ / BM);   // (12, 196) fc1
    const dim3 gR(HID_ / BN, BN_ / BM);    // (12, 49)  rec dense
    const int nb75k = (NC_ + 255) / 256;
    const int nbBNC = (BNC_ + 255) / 256;
    const int nbMH  = (MH_ + 255) / 256;
    const dim3 tb32(32, 8);
    const dim3 gT384(C_ / 32, C_ / 32);
    const dim3 gT1536(HID_ / 32, HID_ / 32);
    const dim3 gTfc2(HID_ / 32, C_ / 32);  // fc2_w [C, HID] -> fc2T [HID, C]

    // ---- weight transposes for gather-SpMM ----
    transpose_k<<<gT384, tb32>>>(ap_w, apT, C_, C_);
    transpose_k<<<gT384, tb32>>>(watt_w, watT, C_, C_);
    transpose_k<<<gT384, tb32>>>(wlsm_w, wlsT, C_, C_);
    transpose_k<<<gT384, tb32>>>(fp_w, fpT, C_, C_);
    transpose_k<<<gT1536, tb32>>>(rec_w, recT, HID_, HID_);
    transpose_k<<<gTfc2, tb32>>>(fc2_w, fc2T, C_, HID_);

    // --- SSA branch ---
    sgemm_nt<<<gC, 256>>>(x, q_w, q_b, bq, TBN_, C_, C_);
    sgemm_nt<<<gC, 256>>>(x, k_w, k_b, bk, TBN_, C_, C_);
    sgemm_nt<<<gC, 256>>>(x, v_w, v_b, bv, TBN_, C_, C_);
    lif_seq3<<<dim3(nb75k, 3), 256>>>(bq, bk, bv, lif_w);

    attn_kernel<<<TB_ * H_, 256>>>(bq, bk, bv, ab);
    lif_seq<<<nbBNC, 256>>>(ab, T_, BNC_, BNC_, lif_w, 3);

    spmm_gather<2><<<TBN_, 256>>>(ab, apT, ap_b, af, C_, C_);
    lif_seq<<<nb75k, 256>>>(af, TB_, NC_, NC_, lif_w, 4);

    // --- LSM branch ---
    sgemm_nt<<<gH, 256>>>(x, fc1_w, fc1_b, curr, TBN_, HID_, C_);
    lsm_step0<<<nbMH, 256>>>(curr, rec_b, syn, mem, spk);
    // t=1, t=2: gather
    spmm_gather<6><<<BN_, 256>>>(spk, recT, rec_b, R, HID_, HID_);
    lsm_step<<<nbMH, 256>>>(curr + (size_t)MH_, R, syn, mem, spk, spk + (size_t)MH_);
    spmm_gather<6><<<BN_, 256>>>(spk + (size_t)MH_, recT, rec_b, R, HID_, HID_);
    lsm_step<<<nbMH, 256>>>(curr + 2 * (size_t)MH_, R, syn, mem,
                            spk + (size_t)MH_, spk + 2 * (size_t)MH_);
    // t=3: dense
    sgemm_nt<<<gR, 256>>>(spk + 2 * (size_t)MH_, rec_w, rec_b, R, BN_, HID_, HID_);
    lsm_step<<<nbMH, 256>>>(curr + 3 * (size_t)MH_, R, syn, mem,
                            spk + 2 * (size_t)MH_, spk + 3 * (size_t)MH_);

    // fc2 split by t: t0/t1 gather (sparse spikes), t2+t3 dense
    spmm_gather<2><<<BN_, 256>>>(spk, fc2T, fc2_b, l, C_, HID_);
    spmm_gather<2><<<BN_, 256>>>(spk + (size_t)MH_, fc2T, fc2_b,
                                 l + (size_t)BN_ * C_, C_, HID_);
    sgemm_nt<<<dim3(C_ / BN, (2 * BN_) / BM), 256>>>(spk + 2 * (size_t)MH_, fc2_w, fc2_b,
                                                     l + 2 * (size_t)BN_ * C_,
                                                     2 * BN_, C_, HID_);
    bn_partial<<<98, 384>>>(l, part);
    bn_finalize<<<1, 384>>>(part, stats);
    bn_lif4<<<nbBNC, 256>>>(l, l, stats, bnl_g, bnl_b, lif_w, 5, nullptr);

    // --- ARIG fusion ---
    spmm_gather<2><<<TBN_, 256>>>(af, watT, watt_b, ga, C_, C_);
    spmm_gather<2><<<TBN_, 256>>>(l, wlsT, wlsm_b, gl, C_, C_);
    fuse_kernel<<<nbMH, 256>>>(af, l, ga, gl, fu);
    spmm_gather_val<2><<<TBN_, 256>>>(fu, fpT, fp_b, o, C_, C_);
    bn_partial<<<98, 384>>>(o, part);
    bn_finalize<<<1, 384>>>(part, stats);
    bn_lif4<<<nbBNC, 256>>>(o, out, stats, bnf_g, bnf_b, lif_w, 6, x);
}